// round 3
// baseline (speedup 1.0000x reference)
#include <cuda_runtime.h>

#define NN    50000
#define EE    200000
#define GG    128
#define FIN   40
#define H512  512
#define H1024 1024
#define FC    2048
#define NCLS  345

// ---------------- scratch (static device globals; no allocations) ----------
__device__ float g_bufA[(size_t)NN * H1024];
__device__ float g_bufB[(size_t)NN * H1024];
__device__ float g_bufC[(size_t)NN * H1024];
__device__ float g_ew[EE];
__device__ float g_norm[EE];
__device__ float g_deg[NN];
__device__ float g_dis[NN];
__device__ float g_pooled[GG * H1024];
__device__ float g_cnt[GG];
__device__ float g_z[GG * FC];
__device__ int   g_is64;   // 1 if index tensors are int64, 0 if int32

// Buffer selector: device-side resolution of scratch symbols (avoids any
// host-side cudaGetSymbolAddress, which the harness environment rejects).
#define BUF_A      0
#define BUF_B      1
#define BUF_C      2
#define BUF_POOLED 3
#define BUF_Z      4
__device__ __forceinline__ float* sel(int id) {
    switch (id) {
        case BUF_A:      return g_bufA;
        case BUF_B:      return g_bufB;
        case BUF_C:      return g_bufC;
        case BUF_POOLED: return g_pooled;
        case BUF_Z:      return g_z;
    }
    return nullptr;
}

// Index load honoring detected dtype.
__device__ __forceinline__ int ld_idx(const void* p, long long i) {
    return g_is64 ? (int)((const long long*)p)[i] : ((const int*)p)[i];
}

// ---------------- dtype detection ------------------------------------------
// edge_index values are uniform in [0, 50000). If stored as int64 (LE), every
// odd 32-bit word is a zero high-half. If int32, odd words are random values.
__global__ void k_detect(const unsigned int* __restrict__ ei_words) {
    __shared__ int found;
    if (threadIdx.x == 0) found = 0;
    __syncthreads();
    for (int i = 1 + 2 * threadIdx.x; i < 4096; i += 2 * blockDim.x)
        if (ei_words[i] != 0u) found = 1;
    __syncthreads();
    if (threadIdx.x == 0) g_is64 = (found ? 0 : 1);
}

// ---------------- init: deg=1 (self loop), zero pooled/cnt -----------------
__global__ void k_init() {
    int i = blockIdx.x * blockDim.x + threadIdx.x;
    if (i < NN) g_deg[i] = 1.0f;
    if (i < GG * H1024) g_pooled[i] = 0.0f;
    if (i < GG) g_cnt[i] = 0.0f;
}

// ---------------- edge MLP: ew = sigmoid(relu(ea@W1+b1)@W2+b2) -------------
__global__ void k_edge_mlp(const float* __restrict__ ea,
                           const float* __restrict__ w1, const float* __restrict__ b1,
                           const float* __restrict__ w2, const float* __restrict__ b2) {
    int e = blockIdx.x * blockDim.x + threadIdx.x;
    if (e >= EE) return;
    float a0 = ea[e * 3 + 0], a1 = ea[e * 3 + 1], a2 = ea[e * 3 + 2];
    float acc = b2[0];
#pragma unroll 8
    for (int h = 0; h < 64; h++) {
        float v = b1[h] + a0 * w1[h] + a1 * w1[64 + h] + a2 * w1[128 + h];
        acc += fmaxf(v, 0.0f) * w2[h];
    }
    g_ew[e] = 1.0f / (1.0f + expf(-acc));
}

// ---------------- degree / dis / per-edge norm ------------------------------
__global__ void k_deg(const void* __restrict__ ei) {
    int e = blockIdx.x * blockDim.x + threadIdx.x;
    if (e >= EE) return;
    int d = ld_idx(ei, (long long)EE + e);
    if (d >= 0 && d < NN) atomicAdd(&g_deg[d], g_ew[e]);
}

__global__ void k_dis() {
    int i = blockIdx.x * blockDim.x + threadIdx.x;
    if (i >= NN) return;
    g_dis[i] = rsqrtf(g_deg[i]);   // deg >= 1 always
}

__global__ void k_norm(const void* __restrict__ ei) {
    int e = blockIdx.x * blockDim.x + threadIdx.x;
    if (e >= EE) return;
    int s = ld_idx(ei, e);
    int d = ld_idx(ei, (long long)EE + e);
    float v = 0.0f;
    if (s >= 0 && s < NN && d >= 0 && d < NN)
        v = g_dis[s] * g_ew[e] * g_dis[d];
    g_norm[e] = v;
}

// ---------------- SGEMM: C = A[MxK] @ B[KxN] (+bias)(+relu) ----------------
// 128x128 block tile, BK=8, 256 threads, 8x8 per-thread microtile.
__global__ __launch_bounds__(256) void k_sgemm(
    const float* Aext, int aId,
    const float* __restrict__ B,
    const float* __restrict__ bias,
    float* Cext, int cId,
    int M, int Ncols, int K, int doRelu)
{
    const float* __restrict__ A = (aId >= 0) ? sel(aId) : Aext;
    float* __restrict__ C       = (cId >= 0) ? sel(cId) : Cext;

    const int BM = 128, BN = 128, BK = 8, TM = 8, TN = 8;
    __shared__ __align__(16) float As[BK][BM];
    __shared__ __align__(16) float Bs[BK][BN];

    int tid = threadIdx.x;
    int blockRow = blockIdx.y * BM;
    int blockCol = blockIdx.x * BN;
    int tr = tid / 16;        // 0..15
    int tc = tid % 16;        // 0..15

    float acc[TM][TN];
#pragma unroll
    for (int i = 0; i < TM; i++)
#pragma unroll
        for (int j = 0; j < TN; j++) acc[i][j] = 0.0f;

    int aRow = tid >> 1;            // 0..127
    int aCol = (tid & 1) * 4;       // 0 or 4
    int bRow = tid >> 5;            // 0..7
    int bCol = (tid & 31) * 4;      // 0..124

    for (int k0 = 0; k0 < K; k0 += BK) {
        int gr = blockRow + aRow;
#pragma unroll
        for (int j = 0; j < 4; j++) {
            int gc = k0 + aCol + j;
            As[aCol + j][aRow] = (gr < M && gc < K) ? A[(long long)gr * K + gc] : 0.0f;
        }
        int br = k0 + bRow;
#pragma unroll
        for (int j = 0; j < 4; j++) {
            int gc = blockCol + bCol + j;
            Bs[bRow][bCol + j] = (br < K && gc < Ncols) ? B[(long long)br * Ncols + gc] : 0.0f;
        }
        __syncthreads();

#pragma unroll
        for (int k = 0; k < BK; k++) {
            float ra[TM], rb[TN];
#pragma unroll
            for (int i = 0; i < TM; i++) ra[i] = As[k][tr * TM + i];
#pragma unroll
            for (int j = 0; j < TN; j++) rb[j] = Bs[k][tc * TN + j];
#pragma unroll
            for (int i = 0; i < TM; i++)
#pragma unroll
                for (int j = 0; j < TN; j++)
                    acc[i][j] += ra[i] * rb[j];
        }
        __syncthreads();
    }

#pragma unroll
    for (int i = 0; i < TM; i++) {
        int gr = blockRow + tr * TM + i;
        if (gr >= M) continue;
#pragma unroll
        for (int j = 0; j < TN; j++) {
            int gc = blockCol + tc * TN + j;
            if (gc >= Ncols) continue;
            float v = acc[i][j];
            if (bias) v += bias[gc];
            if (doRelu) v = fmaxf(v, 0.0f);
            C[(long long)gr * Ncols + gc] = v;
        }
    }
}

// ---------------- aggregation (GCN message passing) ------------------------
// out[i,:] = (1/deg[i]) * t[i,:]   (self-loop term, norm = dis^2)
__global__ void k_agg_init(int tId, int outId) {
    const float* __restrict__ t = sel(tId);
    float* __restrict__ out     = sel(outId);
    long long idx = (long long)blockIdx.x * blockDim.x + threadIdx.x;
    if (idx >= (long long)NN * H1024) return;
    int row = (int)(idx >> 10);
    float d = g_dis[row];
    out[idx] = d * d * t[idx];
}

// out[dst,:] += norm[e] * t[src,:]   (warp per edge)
__global__ void k_agg_edges(int tId, int outId, const void* __restrict__ ei) {
    const float* __restrict__ t = sel(tId);
    float* __restrict__ out     = sel(outId);
    int e = blockIdx.x * (blockDim.x >> 5) + (threadIdx.x >> 5);
    if (e >= EE) return;
    int lane = threadIdx.x & 31;
    int src = ld_idx(ei, e);
    int dst = ld_idx(ei, (long long)EE + e);
    if (src < 0 || src >= NN || dst < 0 || dst >= NN) return;
    float w = g_norm[e];
    const float* trow = t + (long long)src * H1024;
    float* orow = out + (long long)dst * H1024;
#pragma unroll 8
    for (int f = lane; f < H1024; f += 32)
        atomicAdd(&orow[f], w * trow[f]);
}

__global__ void k_bias_relu(int outId, const float* __restrict__ b) {
    float* __restrict__ out = sel(outId);
    long long idx = (long long)blockIdx.x * blockDim.x + threadIdx.x;
    if (idx >= (long long)NN * H1024) return;
    out[idx] = fmaxf(out[idx] + b[idx & (H1024 - 1)], 0.0f);
}

// ---------------- pooling ---------------------------------------------------
__global__ void k_pool(int hId, const void* __restrict__ batch) {
    const float* __restrict__ h = sel(hId);
    int node = blockIdx.x * (blockDim.x >> 5) + (threadIdx.x >> 5);
    if (node >= NN) return;
    int lane = threadIdx.x & 31;
    int g = ld_idx(batch, node);
    if (g < 0 || g >= GG) return;
    const float* row = h + (long long)node * H1024;
    float* prow = g_pooled + g * H1024;
#pragma unroll 8
    for (int f = lane; f < H1024; f += 32)
        atomicAdd(&prow[f], row[f]);
    if (lane == 0) atomicAdd(&g_cnt[g], 1.0f);
}

__global__ void k_pool_div() {
    int idx = blockIdx.x * blockDim.x + threadIdx.x;
    if (idx >= GG * H1024) return;
    g_pooled[idx] /= fmaxf(g_cnt[idx >> 10], 1.0f);
}

// ---------------- host orchestration ---------------------------------------
static void sgemm(const float* Aext, int aId, const float* B, const float* bias,
                  float* Cext, int cId, int M, int N, int K, int relu) {
    dim3 grid((N + 127) / 128, (M + 127) / 128);
    k_sgemm<<<grid, 256>>>(Aext, aId, B, bias, Cext, cId, M, N, K, relu);
}

extern "C" void kernel_launch(void* const* d_in, const int* in_sizes, int n_in,
                              void* d_out, int out_size) {
    const float* x         = (const float*)d_in[0];
    const float* edge_attr = (const float*)d_in[1];
    const void*  ei        = d_in[2];
    const void*  batch     = d_in[3];
    const float *emb_w1 = (const float*)d_in[4],  *emb_b1 = (const float*)d_in[5];
    const float *emb_w2 = (const float*)d_in[6],  *emb_b2 = (const float*)d_in[7];
    const float *ep_w1  = (const float*)d_in[8],  *ep_b1  = (const float*)d_in[9];
    const float *ep_w2  = (const float*)d_in[10], *ep_b2  = (const float*)d_in[11];
    const float *c6_w   = (const float*)d_in[12], *c6_b   = (const float*)d_in[13];
    const float *c7_w   = (const float*)d_in[14], *c7_b   = (const float*)d_in[15];
    const float *c8_w   = (const float*)d_in[16], *c8_b   = (const float*)d_in[17];
    const float *fc1_w  = (const float*)d_in[18], *fc1_b  = (const float*)d_in[19];
    const float *head_w = (const float*)d_in[20], *head_b = (const float*)d_in[21];
    float* out = (float*)d_out;

    const long long NH = (long long)NN * H1024;
    int gNH = (int)((NH + 255) / 256);

    // dtype detection + init + edge weights + normalization coefficients
    k_detect<<<1, 256>>>((const unsigned int*)ei);
    k_init<<<(GG * H1024 + 255) / 256, 256>>>();
    k_edge_mlp<<<(EE + 255) / 256, 256>>>(edge_attr, ep_w1, ep_b1, ep_w2, ep_b2);
    k_deg<<<(EE + 255) / 256, 256>>>(ei);
    k_dis<<<(NN + 255) / 256, 256>>>();
    k_norm<<<(EE + 255) / 256, 256>>>(ei);

    // embedding MLP
    sgemm(x, -1,      emb_w1, emb_b1, nullptr, BUF_C, NN, H512, FIN,  1);  // [N,512]
    sgemm(nullptr, BUF_C, emb_w2, emb_b2, nullptr, BUF_B, NN, H512, H512, 1);

    // conv1: 512 -> 1024
    sgemm(nullptr, BUF_B, c6_w, nullptr, nullptr, BUF_A, NN, H1024, H512, 0);
    k_agg_init<<<gNH, 256>>>(BUF_A, BUF_C);
    k_agg_edges<<<(EE + 7) / 8, 256>>>(BUF_A, BUF_C, ei);
    k_bias_relu<<<gNH, 256>>>(BUF_C, c6_b);

    // conv2: 1024 -> 1024
    sgemm(nullptr, BUF_C, c7_w, nullptr, nullptr, BUF_A, NN, H1024, H1024, 0);
    k_agg_init<<<gNH, 256>>>(BUF_A, BUF_B);
    k_agg_edges<<<(EE + 7) / 8, 256>>>(BUF_A, BUF_B, ei);
    k_bias_relu<<<gNH, 256>>>(BUF_B, c7_b);

    // conv3: 1024 -> 1024
    sgemm(nullptr, BUF_B, c8_w, nullptr, nullptr, BUF_A, NN, H1024, H1024, 0);
    k_agg_init<<<gNH, 256>>>(BUF_A, BUF_C);
    k_agg_edges<<<(EE + 7) / 8, 256>>>(BUF_A, BUF_C, ei);
    k_bias_relu<<<gNH, 256>>>(BUF_C, c8_b);

    // mean pool over graphs
    k_pool<<<(NN + 7) / 8, 256>>>(BUF_C, batch);
    k_pool_div<<<(GG * H1024 + 255) / 256, 256>>>();

    // head
    sgemm(nullptr, BUF_POOLED, fc1_w, fc1_b, nullptr, BUF_Z, GG, FC, H1024, 1);
    sgemm(nullptr, BUF_Z, head_w, head_b, out, -1, GG, NCLS, FC, 0);
}

// round 5
// speedup vs baseline: 1.8146x; 1.8146x over previous
#include <cuda_runtime.h>
#include <cstdint>

#define NN    50000
#define EE    200000
#define GG    128
#define FIN   40
#define H512  512
#define H1024 1024
#define FC    2048
#define NCLS  345

// ---------------- scratch (static device globals; no allocations) ----------
__device__ float g_bufA[(size_t)NN * H1024];
__device__ float g_bufB[(size_t)NN * H1024];
__device__ float g_bufC[(size_t)NN * H1024];
__device__ float g_ew[EE];
__device__ float g_norm[EE];
__device__ float g_deg[NN];
__device__ float g_dis[NN];
__device__ float g_pooled[GG * H1024];
__device__ float g_cnt[GG];
__device__ float g_z[GG * FC];
__device__ int   g_is64;   // 1 if index tensors are int64, 0 if int32

#define BUF_A      0
#define BUF_B      1
#define BUF_C      2
#define BUF_POOLED 3
#define BUF_Z      4
__device__ __forceinline__ float* sel(int id) {
    switch (id) {
        case BUF_A:      return g_bufA;
        case BUF_B:      return g_bufB;
        case BUF_C:      return g_bufC;
        case BUF_POOLED: return g_pooled;
        case BUF_Z:      return g_z;
    }
    return nullptr;
}

__device__ __forceinline__ int ld_idx(const void* p, long long i) {
    return g_is64 ? (int)((const long long*)p)[i] : ((const int*)p)[i];
}

__device__ __forceinline__ uint32_t f2tf(float x) {
    uint32_t u;
    asm("cvt.rna.tf32.f32 %0, %1;" : "=r"(u) : "f"(x));
    return u;
}

// ---------------- dtype detection ------------------------------------------
__global__ void k_detect(const unsigned int* __restrict__ ei_words) {
    __shared__ int found;
    if (threadIdx.x == 0) found = 0;
    __syncthreads();
    for (int i = 1 + 2 * threadIdx.x; i < 4096; i += 2 * blockDim.x)
        if (ei_words[i] != 0u) found = 1;
    __syncthreads();
    if (threadIdx.x == 0) g_is64 = (found ? 0 : 1);
}

// ---------------- init ------------------------------------------------------
__global__ void k_init() {
    int i = blockIdx.x * blockDim.x + threadIdx.x;
    if (i < NN) g_deg[i] = 1.0f;
    if (i < GG * H1024) g_pooled[i] = 0.0f;
    if (i < GG) g_cnt[i] = 0.0f;
}

// ---------------- edge MLP --------------------------------------------------
__global__ void k_edge_mlp(const float* __restrict__ ea,
                           const float* __restrict__ w1, const float* __restrict__ b1,
                           const float* __restrict__ w2, const float* __restrict__ b2) {
    int e = blockIdx.x * blockDim.x + threadIdx.x;
    if (e >= EE) return;
    float a0 = ea[e * 3 + 0], a1 = ea[e * 3 + 1], a2 = ea[e * 3 + 2];
    float acc = b2[0];
#pragma unroll 8
    for (int h = 0; h < 64; h++) {
        float v = b1[h] + a0 * w1[h] + a1 * w1[64 + h] + a2 * w1[128 + h];
        acc += fmaxf(v, 0.0f) * w2[h];
    }
    g_ew[e] = 1.0f / (1.0f + expf(-acc));
}

// ---------------- degree / dis / per-edge norm ------------------------------
__global__ void k_deg(const void* __restrict__ ei) {
    int e = blockIdx.x * blockDim.x + threadIdx.x;
    if (e >= EE) return;
    int d = ld_idx(ei, (long long)EE + e);
    if (d >= 0 && d < NN) atomicAdd(&g_deg[d], g_ew[e]);
}

__global__ void k_dis() {
    int i = blockIdx.x * blockDim.x + threadIdx.x;
    if (i >= NN) return;
    g_dis[i] = rsqrtf(g_deg[i]);
}

__global__ void k_norm(const void* __restrict__ ei) {
    int e = blockIdx.x * blockDim.x + threadIdx.x;
    if (e >= EE) return;
    int s = ld_idx(ei, e);
    int d = ld_idx(ei, (long long)EE + e);
    float v = 0.0f;
    if (s >= 0 && s < NN && d >= 0 && d < NN)
        v = g_dis[s] * g_ew[e] * g_dis[d];
    g_norm[e] = v;
}

// ---------------- tf32 tensor-core GEMM -------------------------------------
// C = A[MxK] @ B[KxN] (+bias)(+relu). Optional second output:
// S[r,c] = dis[r]^2 * C_raw[r,c]  (self-loop init for GCN aggregation).
// CTA tile 128x128, BK=16, 8 warps, warp tile 64x32 (4x4 m16n8k8 mmas).
__global__ __launch_bounds__(256) void k_tf32gemm(
    const float* Aext, int aId,
    const float* __restrict__ B,
    const float* __restrict__ bias,
    float* Cext, int cId, int sId,
    int M, int N, int K, int doRelu)
{
    const float* __restrict__ A = (aId >= 0) ? sel(aId) : Aext;
    float* __restrict__ C       = (cId >= 0) ? sel(cId) : Cext;
    float* __restrict__ S       = (sId >= 0) ? sel(sId) : nullptr;

    __shared__ uint32_t As[16][132];   // [k][m], tf32 bits
    __shared__ uint32_t Bs[16][132];   // [k][n], tf32 bits

    const int tid  = threadIdx.x;
    const int wid  = tid >> 5;
    const int lane = tid & 31;
    const int grp  = lane >> 2;    // 0..7
    const int tg   = lane & 3;     // 0..3
    const int warp_m = wid & 1;    // 2 warps along M (64 rows each)
    const int warp_n = wid >> 1;   // 4 warps along N (32 cols each)

    const int blockRow = blockIdx.y * 128;
    const int blockCol = blockIdx.x * 128;
    const bool nAligned = ((N & 3) == 0);

    float acc[4][4][4];
#pragma unroll
    for (int mi = 0; mi < 4; mi++)
#pragma unroll
        for (int ni = 0; ni < 4; ni++)
#pragma unroll
            for (int r = 0; r < 4; r++) acc[mi][ni][r] = 0.0f;

    const int kIters = (K + 15) / 16;
    for (int it = 0; it < kIters; it++) {
        const int k0 = it * 16;

        // load A tile 128x16 -> As[k][m] (transposed), tf32-converted
#pragma unroll
        for (int i = 0; i < 2; i++) {
            int idx = tid + i * 256;          // 0..511 float4 slots
            int row = idx >> 2;               // 0..127
            int c4  = (idx & 3) << 2;         // 0,4,8,12
            int gr = blockRow + row;
            int gk = k0 + c4;
            float v0 = 0, v1 = 0, v2 = 0, v3 = 0;
            if (gr < M) {
                const float* ap = A + (long long)gr * K + gk;
                if (gk + 3 < K) {
                    float4 v = *(const float4*)ap;
                    v0 = v.x; v1 = v.y; v2 = v.z; v3 = v.w;
                } else {
                    if (gk + 0 < K) v0 = ap[0];
                    if (gk + 1 < K) v1 = ap[1];
                    if (gk + 2 < K) v2 = ap[2];
                    if (gk + 3 < K) v3 = ap[3];
                }
            }
            As[c4 + 0][row] = f2tf(v0);
            As[c4 + 1][row] = f2tf(v1);
            As[c4 + 2][row] = f2tf(v2);
            As[c4 + 3][row] = f2tf(v3);
        }
        // load B tile 16x128 -> Bs[k][n]
#pragma unroll
        for (int i = 0; i < 2; i++) {
            int idx = tid + i * 256;
            int row = idx >> 5;               // 0..15 (k)
            int c4  = (idx & 31) << 2;        // 0..124 (n)
            int gk = k0 + row;
            int gc = blockCol + c4;
            float v0 = 0, v1 = 0, v2 = 0, v3 = 0;
            if (gk < K) {
                const float* bp = B + (long long)gk * N + gc;
                if (nAligned && gc + 3 < N) {
                    float4 v = *(const float4*)bp;
                    v0 = v.x; v1 = v.y; v2 = v.z; v3 = v.w;
                } else {
                    if (gc + 0 < N) v0 = bp[0];
                    if (gc + 1 < N) v1 = bp[1];
                    if (gc + 2 < N) v2 = bp[2];
                    if (gc + 3 < N) v3 = bp[3];
                }
            }
            Bs[row][c4 + 0] = f2tf(v0);
            Bs[row][c4 + 1] = f2tf(v1);
            Bs[row][c4 + 2] = f2tf(v2);
            Bs[row][c4 + 3] = f2tf(v3);
        }
        __syncthreads();

#pragma unroll
        for (int ks = 0; ks < 2; ks++) {
            const int kb = ks * 8;
            uint32_t af[4][4], bf[4][2];
#pragma unroll
            for (int mi = 0; mi < 4; mi++) {
                int rb = warp_m * 64 + mi * 16;
                af[mi][0] = As[kb + tg][rb + grp];
                af[mi][1] = As[kb + tg][rb + grp + 8];
                af[mi][2] = As[kb + tg + 4][rb + grp];
                af[mi][3] = As[kb + tg + 4][rb + grp + 8];
            }
#pragma unroll
            for (int ni = 0; ni < 4; ni++) {
                int nb = warp_n * 32 + ni * 8;
                bf[ni][0] = Bs[kb + tg][nb + grp];
                bf[ni][1] = Bs[kb + tg + 4][nb + grp];
            }
#pragma unroll
            for (int mi = 0; mi < 4; mi++)
#pragma unroll
                for (int ni = 0; ni < 4; ni++) {
                    asm volatile(
                        "mma.sync.aligned.m16n8k8.row.col.f32.tf32.tf32.f32 "
                        "{%0,%1,%2,%3}, {%4,%5,%6,%7}, {%8,%9}, {%0,%1,%2,%3};\n"
                        : "+f"(acc[mi][ni][0]), "+f"(acc[mi][ni][1]),
                          "+f"(acc[mi][ni][2]), "+f"(acc[mi][ni][3])
                        : "r"(af[mi][0]), "r"(af[mi][1]), "r"(af[mi][2]), "r"(af[mi][3]),
                          "r"(bf[ni][0]), "r"(bf[ni][1]));
                }
        }
        __syncthreads();
    }

    // epilogue
#pragma unroll
    for (int mi = 0; mi < 4; mi++) {
        int r0 = blockRow + warp_m * 64 + mi * 16 + grp;
        int r1 = r0 + 8;
        float s0 = 0.f, s1 = 0.f;
        if (S) {
            if (r0 < M) { float d = g_dis[r0]; s0 = d * d; }
            if (r1 < M) { float d = g_dis[r1]; s1 = d * d; }
        }
#pragma unroll
        for (int ni = 0; ni < 4; ni++) {
            int c0 = blockCol + warp_n * 32 + ni * 8 + 2 * tg;
            int c1 = c0 + 1;
#pragma unroll
            for (int h = 0; h < 2; h++) {
                int c = h ? c1 : c0;
                if (c >= N) continue;
                float b = bias ? bias[c] : 0.0f;
                if (r0 < M) {
                    float v = acc[mi][ni][h] + b;
                    if (doRelu) v = fmaxf(v, 0.0f);
                    C[(long long)r0 * N + c] = v;
                    if (S) S[(long long)r0 * N + c] = s0 * v;
                }
                if (r1 < M) {
                    float v = acc[mi][ni][2 + h] + b;
                    if (doRelu) v = fmaxf(v, 0.0f);
                    C[(long long)r1 * N + c] = v;
                    if (S) S[(long long)r1 * N + c] = s1 * v;
                }
            }
        }
    }
}

// ---------------- aggregation: out[dst,:] += norm[e] * t[src,:] -------------
__global__ void k_agg_edges(int tId, int outId, const void* __restrict__ ei) {
    const float* __restrict__ t = sel(tId);
    float* __restrict__ out     = sel(outId);
    int e = blockIdx.x * (blockDim.x >> 5) + (threadIdx.x >> 5);
    if (e >= EE) return;
    int lane = threadIdx.x & 31;
    int src = ld_idx(ei, e);
    int dst = ld_idx(ei, (long long)EE + e);
    if (src < 0 || src >= NN || dst < 0 || dst >= NN) return;
    float w = g_norm[e];
    const float* trow = t + (long long)src * H1024;
    float* orow = out + (long long)dst * H1024;
#pragma unroll 8
    for (int f = lane; f < H1024; f += 32)
        atomicAdd(&orow[f], w * trow[f]);
}

__global__ void k_bias_relu(int outId, const float* __restrict__ b) {
    float* __restrict__ out = sel(outId);
    long long idx = (long long)blockIdx.x * blockDim.x + threadIdx.x;
    if (idx >= (long long)NN * H1024) return;
    out[idx] = fmaxf(out[idx] + b[idx & (H1024 - 1)], 0.0f);
}

// ---------------- pooling ---------------------------------------------------
__global__ void k_pool(int hId, const void* __restrict__ batch) {
    const float* __restrict__ h = sel(hId);
    int node = blockIdx.x * (blockDim.x >> 5) + (threadIdx.x >> 5);
    if (node >= NN) return;
    int lane = threadIdx.x & 31;
    int g = ld_idx(batch, node);
    if (g < 0 || g >= GG) return;
    const float* row = h + (long long)node * H1024;
    float* prow = g_pooled + g * H1024;
#pragma unroll 8
    for (int f = lane; f < H1024; f += 32)
        atomicAdd(&prow[f], row[f]);
    if (lane == 0) atomicAdd(&g_cnt[g], 1.0f);
}

__global__ void k_pool_div() {
    int idx = blockIdx.x * blockDim.x + threadIdx.x;
    if (idx >= GG * H1024) return;
    g_pooled[idx] /= fmaxf(g_cnt[idx >> 10], 1.0f);
}

// ---------------- host orchestration ---------------------------------------
static void gemm(const float* Aext, int aId, const float* B, const float* bias,
                 float* Cext, int cId, int sId, int M, int N, int K, int relu) {
    dim3 grid((N + 127) / 128, (M + 127) / 128);
    k_tf32gemm<<<grid, 256>>>(Aext, aId, B, bias, Cext, cId, sId, M, N, K, relu);
}

extern "C" void kernel_launch(void* const* d_in, const int* in_sizes, int n_in,
                              void* d_out, int out_size) {
    const float* x         = (const float*)d_in[0];
    const float* edge_attr = (const float*)d_in[1];
    const void*  ei        = d_in[2];
    const void*  batch     = d_in[3];
    const float *emb_w1 = (const float*)d_in[4],  *emb_b1 = (const float*)d_in[5];
    const float *emb_w2 = (const float*)d_in[6],  *emb_b2 = (const float*)d_in[7];
    const float *ep_w1  = (const float*)d_in[8],  *ep_b1  = (const float*)d_in[9];
    const float *ep_w2  = (const float*)d_in[10], *ep_b2  = (const float*)d_in[11];
    const float *c6_w   = (const float*)d_in[12], *c6_b   = (const float*)d_in[13];
    const float *c7_w   = (const float*)d_in[14], *c7_b   = (const float*)d_in[15];
    const float *c8_w   = (const float*)d_in[16], *c8_b   = (const float*)d_in[17];
    const float *fc1_w  = (const float*)d_in[18], *fc1_b  = (const float*)d_in[19];
    const float *head_w = (const float*)d_in[20], *head_b = (const float*)d_in[21];
    float* out = (float*)d_out;

    const long long NH = (long long)NN * H1024;
    int gNH = (int)((NH + 255) / 256);

    k_detect<<<1, 256>>>((const unsigned int*)ei);
    k_init<<<(GG * H1024 + 255) / 256, 256>>>();
    k_edge_mlp<<<(EE + 255) / 256, 256>>>(edge_attr, ep_w1, ep_b1, ep_w2, ep_b2);
    k_deg<<<(EE + 255) / 256, 256>>>(ei);
    k_dis<<<(NN + 255) / 256, 256>>>();
    k_norm<<<(EE + 255) / 256, 256>>>(ei);

    // embedding MLP
    gemm(x, -1,          emb_w1, emb_b1, nullptr, BUF_C, -1, NN, H512, FIN,  1);
    gemm(nullptr, BUF_C, emb_w2, emb_b2, nullptr, BUF_B, -1, NN, H512, H512, 1);

    // conv1: 512 -> 1024 (raw t -> BUF_A, self-loop-scaled -> BUF_C)
    gemm(nullptr, BUF_B, c6_w, nullptr, nullptr, BUF_A, BUF_C, NN, H1024, H512, 0);
    k_agg_edges<<<(EE + 7) / 8, 256>>>(BUF_A, BUF_C, ei);
    k_bias_relu<<<gNH, 256>>>(BUF_C, c6_b);

    // conv2: 1024 -> 1024
    gemm(nullptr, BUF_C, c7_w, nullptr, nullptr, BUF_A, BUF_B, NN, H1024, H1024, 0);
    k_agg_edges<<<(EE + 7) / 8, 256>>>(BUF_A, BUF_B, ei);
    k_bias_relu<<<gNH, 256>>>(BUF_B, c7_b);

    // conv3: 1024 -> 1024
    gemm(nullptr, BUF_B, c8_w, nullptr, nullptr, BUF_A, BUF_C, NN, H1024, H1024, 0);
    k_agg_edges<<<(EE + 7) / 8, 256>>>(BUF_A, BUF_C, ei);
    k_bias_relu<<<gNH, 256>>>(BUF_C, c8_b);

    // mean pool
    k_pool<<<(NN + 7) / 8, 256>>>(BUF_C, batch);
    k_pool_div<<<(GG * H1024 + 255) / 256, 256>>>();

    // head
    gemm(nullptr, BUF_POOLED, fc1_w, fc1_b, nullptr, BUF_Z, -1, GG, FC, H1024, 1);
    gemm(nullptr, BUF_Z, head_w, head_b, out, -1, -1, GG, NCLS, FC, 0);
}

// round 6
// speedup vs baseline: 2.3085x; 1.2721x over previous
#include <cuda_runtime.h>
#include <cstdint>

#define NN    50000
#define EE    200000
#define GG    128
#define FIN   40
#define H512  512
#define H1024 1024
#define FC    2048
#define NCLS  345
#define NB_SCAN ((NN + 255) / 256)

// ---------------- scratch (static device globals; no allocations) ----------
__device__ float g_bufA[(size_t)NN * H1024];
__device__ float g_bufB[(size_t)NN * H1024];
__device__ float g_bufC[(size_t)NN * H1024];
__device__ float g_ew[EE];
__device__ float g_deg[NN];
__device__ float g_dis[NN];
__device__ float g_pooled[GG * H1024];
__device__ float g_z[GG * FC];
__device__ int   g_is64;

// CSR (by destination)
__device__ int   g_ecnt[NN];      // in-degree (edges only)
__device__ int   g_rowstart[NN];  // exclusive prefix of g_ecnt
__device__ int   g_next[NN];      // fill cursor
__device__ int   g_csr_src[EE];
__device__ float g_csr_w[EE];
__device__ int   g_blksum[NB_SCAN];

#define BUF_A      0
#define BUF_B      1
#define BUF_C      2
#define BUF_POOLED 3
#define BUF_Z      4
__device__ __forceinline__ float* sel(int id) {
    switch (id) {
        case BUF_A:      return g_bufA;
        case BUF_B:      return g_bufB;
        case BUF_C:      return g_bufC;
        case BUF_POOLED: return g_pooled;
        case BUF_Z:      return g_z;
    }
    return nullptr;
}

__device__ __forceinline__ int ld_idx(const void* p, long long i) {
    return g_is64 ? (int)((const long long*)p)[i] : ((const int*)p)[i];
}

__device__ __forceinline__ uint32_t f2tf(float x) {
    uint32_t u;
    asm("cvt.rna.tf32.f32 %0, %1;" : "=r"(u) : "f"(x));
    return u;
}

// ---------------- dtype detection ------------------------------------------
__global__ void k_detect(const unsigned int* __restrict__ ei_words) {
    __shared__ int found;
    if (threadIdx.x == 0) found = 0;
    __syncthreads();
    for (int i = 1 + 2 * threadIdx.x; i < 4096; i += 2 * blockDim.x)
        if (ei_words[i] != 0u) found = 1;
    __syncthreads();
    if (threadIdx.x == 0) g_is64 = (found ? 0 : 1);
}

// ---------------- init ------------------------------------------------------
__global__ void k_init() {
    int i = blockIdx.x * blockDim.x + threadIdx.x;
    if (i < NN) { g_deg[i] = 1.0f; g_ecnt[i] = 0; }
}

// ---------------- edge MLP --------------------------------------------------
__global__ void k_edge_mlp(const float* __restrict__ ea,
                           const float* __restrict__ w1, const float* __restrict__ b1,
                           const float* __restrict__ w2, const float* __restrict__ b2) {
    int e = blockIdx.x * blockDim.x + threadIdx.x;
    if (e >= EE) return;
    float a0 = ea[e * 3 + 0], a1 = ea[e * 3 + 1], a2 = ea[e * 3 + 2];
    float acc = b2[0];
#pragma unroll 8
    for (int h = 0; h < 64; h++) {
        float v = b1[h] + a0 * w1[h] + a1 * w1[64 + h] + a2 * w1[128 + h];
        acc += fmaxf(v, 0.0f) * w2[h];
    }
    g_ew[e] = 1.0f / (1.0f + expf(-acc));
}

// ---------------- degree (weighted) + in-edge count --------------------------
__global__ void k_degcnt(const void* __restrict__ ei) {
    int e = blockIdx.x * blockDim.x + threadIdx.x;
    if (e >= EE) return;
    int d = ld_idx(ei, (long long)EE + e);
    if (d >= 0 && d < NN) {
        atomicAdd(&g_deg[d], g_ew[e]);
        atomicAdd(&g_ecnt[d], 1);
    }
}

__global__ void k_dis() {
    int i = blockIdx.x * blockDim.x + threadIdx.x;
    if (i >= NN) return;
    g_dis[i] = rsqrtf(g_deg[i]);
}

// ---------------- CSR build: scan of ecnt ------------------------------------
__global__ void k_scan_block() {
    __shared__ int s[256];
    int tid = threadIdx.x;
    int i = blockIdx.x * 256 + tid;
    int v = (i < NN) ? g_ecnt[i] : 0;
    s[tid] = v;
    __syncthreads();
#pragma unroll
    for (int off = 1; off < 256; off <<= 1) {
        int t = (tid >= off) ? s[tid - off] : 0;
        __syncthreads();
        s[tid] += t;
        __syncthreads();
    }
    if (i < NN) g_rowstart[i] = s[tid] - v;
    if (tid == 255) g_blksum[blockIdx.x] = s[tid];
}

__global__ void k_scan_tops() {
    if (threadIdx.x == 0 && blockIdx.x == 0) {
        int run = 0;
        for (int b = 0; b < NB_SCAN; b++) {
            int t = g_blksum[b];
            g_blksum[b] = run;
            run += t;
        }
    }
}

__global__ void k_scan_add() {
    int i = blockIdx.x * 256 + threadIdx.x;
    if (i >= NN) return;
    int r = g_rowstart[i] + g_blksum[blockIdx.x];
    g_rowstart[i] = r;
    g_next[i] = r;
}

__global__ void k_fill(const void* __restrict__ ei) {
    int e = blockIdx.x * blockDim.x + threadIdx.x;
    if (e >= EE) return;
    int s = ld_idx(ei, e);
    int d = ld_idx(ei, (long long)EE + e);
    if (s < 0 || s >= NN || d < 0 || d >= NN) return;
    int pos = atomicAdd(&g_next[d], 1);
    g_csr_src[pos] = s;
    g_csr_w[pos]   = g_dis[s] * g_ew[e] * g_dis[d];
}

// ---------------- tf32 tensor-core GEMM -------------------------------------
// C = A[MxK] @ B[KxN] (+bias)(+relu).
// CTA tile 128x128, BK=16, 8 warps, warp tile 64x32 (4x4 m16n8k8 mmas).
__global__ __launch_bounds__(256) void k_tf32gemm(
    const float* Aext, int aId,
    const float* __restrict__ B,
    const float* __restrict__ bias,
    float* Cext, int cId,
    int M, int N, int K, int doRelu)
{
    const float* __restrict__ A = (aId >= 0) ? sel(aId) : Aext;
    float* __restrict__ C       = (cId >= 0) ? sel(cId) : Cext;

    __shared__ uint32_t As[16][132];   // [k][m], tf32 bits
    __shared__ uint32_t Bs[16][132];   // [k][n], tf32 bits

    const int tid  = threadIdx.x;
    const int wid  = tid >> 5;
    const int lane = tid & 31;
    const int grp  = lane >> 2;
    const int tg   = lane & 3;
    const int warp_m = wid & 1;
    const int warp_n = wid >> 1;

    const int blockRow = blockIdx.y * 128;
    const int blockCol = blockIdx.x * 128;
    const bool nAligned = ((N & 3) == 0);

    float acc[4][4][4];
#pragma unroll
    for (int mi = 0; mi < 4; mi++)
#pragma unroll
        for (int ni = 0; ni < 4; ni++)
#pragma unroll
            for (int r = 0; r < 4; r++) acc[mi][ni][r] = 0.0f;

    const int kIters = (K + 15) / 16;
    for (int it = 0; it < kIters; it++) {
        const int k0 = it * 16;

#pragma unroll
        for (int i = 0; i < 2; i++) {
            int idx = tid + i * 256;
            int row = idx >> 2;
            int c4  = (idx & 3) << 2;
            int gr = blockRow + row;
            int gk = k0 + c4;
            float v0 = 0, v1 = 0, v2 = 0, v3 = 0;
            if (gr < M) {
                const float* ap = A + (long long)gr * K + gk;
                if (gk + 3 < K) {
                    float4 v = *(const float4*)ap;
                    v0 = v.x; v1 = v.y; v2 = v.z; v3 = v.w;
                } else {
                    if (gk + 0 < K) v0 = ap[0];
                    if (gk + 1 < K) v1 = ap[1];
                    if (gk + 2 < K) v2 = ap[2];
                    if (gk + 3 < K) v3 = ap[3];
                }
            }
            As[c4 + 0][row] = f2tf(v0);
            As[c4 + 1][row] = f2tf(v1);
            As[c4 + 2][row] = f2tf(v2);
            As[c4 + 3][row] = f2tf(v3);
        }
#pragma unroll
        for (int i = 0; i < 2; i++) {
            int idx = tid + i * 256;
            int row = idx >> 5;
            int c4  = (idx & 31) << 2;
            int gk = k0 + row;
            int gc = blockCol + c4;
            float v0 = 0, v1 = 0, v2 = 0, v3 = 0;
            if (gk < K) {
                const float* bp = B + (long long)gk * N + gc;
                if (nAligned && gc + 3 < N) {
                    float4 v = *(const float4*)bp;
                    v0 = v.x; v1 = v.y; v2 = v.z; v3 = v.w;
                } else {
                    if (gc + 0 < N) v0 = bp[0];
                    if (gc + 1 < N) v1 = bp[1];
                    if (gc + 2 < N) v2 = bp[2];
                    if (gc + 3 < N) v3 = bp[3];
                }
            }
            Bs[row][c4 + 0] = f2tf(v0);
            Bs[row][c4 + 1] = f2tf(v1);
            Bs[row][c4 + 2] = f2tf(v2);
            Bs[row][c4 + 3] = f2tf(v3);
        }
        __syncthreads();

#pragma unroll
        for (int ks = 0; ks < 2; ks++) {
            const int kb = ks * 8;
            uint32_t af[4][4], bf[4][2];
#pragma unroll
            for (int mi = 0; mi < 4; mi++) {
                int rb = warp_m * 64 + mi * 16;
                af[mi][0] = As[kb + tg][rb + grp];
                af[mi][1] = As[kb + tg][rb + grp + 8];
                af[mi][2] = As[kb + tg + 4][rb + grp];
                af[mi][3] = As[kb + tg + 4][rb + grp + 8];
            }
#pragma unroll
            for (int ni = 0; ni < 4; ni++) {
                int nb = warp_n * 32 + ni * 8;
                bf[ni][0] = Bs[kb + tg][nb + grp];
                bf[ni][1] = Bs[kb + tg + 4][nb + grp];
            }
#pragma unroll
            for (int mi = 0; mi < 4; mi++)
#pragma unroll
                for (int ni = 0; ni < 4; ni++) {
                    asm volatile(
                        "mma.sync.aligned.m16n8k8.row.col.f32.tf32.tf32.f32 "
                        "{%0,%1,%2,%3}, {%4,%5,%6,%7}, {%8,%9}, {%0,%1,%2,%3};\n"
                        : "+f"(acc[mi][ni][0]), "+f"(acc[mi][ni][1]),
                          "+f"(acc[mi][ni][2]), "+f"(acc[mi][ni][3])
                        : "r"(af[mi][0]), "r"(af[mi][1]), "r"(af[mi][2]), "r"(af[mi][3]),
                          "r"(bf[ni][0]), "r"(bf[ni][1]));
                }
        }
        __syncthreads();
    }

#pragma unroll
    for (int mi = 0; mi < 4; mi++) {
        int r0 = blockRow + warp_m * 64 + mi * 16 + grp;
        int r1 = r0 + 8;
#pragma unroll
        for (int ni = 0; ni < 4; ni++) {
            int c0 = blockCol + warp_n * 32 + ni * 8 + 2 * tg;
            int c1 = c0 + 1;
#pragma unroll
            for (int h = 0; h < 2; h++) {
                int c = h ? c1 : c0;
                if (c >= N) continue;
                float b = bias ? bias[c] : 0.0f;
                if (r0 < M) {
                    float v = acc[mi][ni][h] + b;
                    if (doRelu) v = fmaxf(v, 0.0f);
                    C[(long long)r0 * N + c] = v;
                }
                if (r1 < M) {
                    float v = acc[mi][ni][2 + h] + b;
                    if (doRelu) v = fmaxf(v, 0.0f);
                    C[(long long)r1 * N + c] = v;
                }
            }
        }
    }
}

// ---------------- fused gather aggregation (F = 1024) ------------------------
// out[node,:] = relu(bias + dis[node]^2 * t[node,:] + sum_in w * t[src,:])
__global__ __launch_bounds__(256) void k_gather(int tId, int outId,
                                                const float* __restrict__ bias) {
    const float4* __restrict__ t4 = (const float4*)sel(tId);
    float4* __restrict__ o4       = (float4*)sel(outId);
    const float4* __restrict__ b4 = (const float4*)bias;

    int node = blockIdx.x;
    int tid  = threadIdx.x;

    float d = g_dis[node];
    float sw = d * d;
    float4 v = t4[(long long)node * 256 + tid];
    float4 acc;
    acc.x = sw * v.x; acc.y = sw * v.y; acc.z = sw * v.z; acc.w = sw * v.w;

    int s = g_rowstart[node];
    int e = s + g_ecnt[node];
    for (int i = s; i < e; i++) {
        int src = g_csr_src[i];
        float w = g_csr_w[i];
        float4 u = t4[(long long)src * 256 + tid];
        acc.x += w * u.x; acc.y += w * u.y; acc.z += w * u.z; acc.w += w * u.w;
    }
    float4 b = b4[tid];
    acc.x = fmaxf(acc.x + b.x, 0.0f);
    acc.y = fmaxf(acc.y + b.y, 0.0f);
    acc.z = fmaxf(acc.z + b.z, 0.0f);
    acc.w = fmaxf(acc.w + b.w, 0.0f);
    o4[(long long)node * 256 + tid] = acc;
}

// ---------------- segmented mean pooling (batch sorted) ----------------------
__global__ void k_pool2(int hId, const void* __restrict__ batch) {
    const float* __restrict__ h = sel(hId);
    int g = blockIdx.x;          // graph id
    int f = blockIdx.y * 256 + threadIdx.x;   // feature

    // binary search [start, end) of graph g in sorted batch
    int lo = 0, hi = NN;
    while (lo < hi) { int mid = (lo + hi) >> 1; if (ld_idx(batch, mid) < g) lo = mid + 1; else hi = mid; }
    int start = lo;
    lo = start; hi = NN;
    while (lo < hi) { int mid = (lo + hi) >> 1; if (ld_idx(batch, mid) < g + 1) lo = mid + 1; else hi = mid; }
    int end = lo;

    float acc = 0.0f;
    for (int n = start; n < end; n++)
        acc += h[(long long)n * H1024 + f];
    float cnt = (float)(end - start);
    g_pooled[g * H1024 + f] = acc / fmaxf(cnt, 1.0f);
}

// ---------------- host orchestration ---------------------------------------
static void gemm(const float* Aext, int aId, const float* B, const float* bias,
                 float* Cext, int cId, int M, int N, int K, int relu) {
    dim3 grid((N + 127) / 128, (M + 127) / 128);
    k_tf32gemm<<<grid, 256>>>(Aext, aId, B, bias, Cext, cId, M, N, K, relu);
}

extern "C" void kernel_launch(void* const* d_in, const int* in_sizes, int n_in,
                              void* d_out, int out_size) {
    const float* x         = (const float*)d_in[0];
    const float* edge_attr = (const float*)d_in[1];
    const void*  ei        = d_in[2];
    const void*  batch     = d_in[3];
    const float *emb_w1 = (const float*)d_in[4],  *emb_b1 = (const float*)d_in[5];
    const float *emb_w2 = (const float*)d_in[6],  *emb_b2 = (const float*)d_in[7];
    const float *ep_w1  = (const float*)d_in[8],  *ep_b1  = (const float*)d_in[9];
    const float *ep_w2  = (const float*)d_in[10], *ep_b2  = (const float*)d_in[11];
    const float *c6_w   = (const float*)d_in[12], *c6_b   = (const float*)d_in[13];
    const float *c7_w   = (const float*)d_in[14], *c7_b   = (const float*)d_in[15];
    const float *c8_w   = (const float*)d_in[16], *c8_b   = (const float*)d_in[17];
    const float *fc1_w  = (const float*)d_in[18], *fc1_b  = (const float*)d_in[19];
    const float *head_w = (const float*)d_in[20], *head_b = (const float*)d_in[21];
    float* out = (float*)d_out;

    // dtype detect + graph preprocessing (shared by all 3 convs)
    k_detect<<<1, 256>>>((const unsigned int*)ei);
    k_init<<<NB_SCAN, 256>>>();
    k_edge_mlp<<<(EE + 255) / 256, 256>>>(edge_attr, ep_w1, ep_b1, ep_w2, ep_b2);
    k_degcnt<<<(EE + 255) / 256, 256>>>(ei);
    k_dis<<<NB_SCAN, 256>>>();
    k_scan_block<<<NB_SCAN, 256>>>();
    k_scan_tops<<<1, 32>>>();
    k_scan_add<<<NB_SCAN, 256>>>();
    k_fill<<<(EE + 255) / 256, 256>>>(ei);

    // embedding MLP
    gemm(x, -1,          emb_w1, emb_b1, nullptr, BUF_C, NN, H512, FIN,  1);
    gemm(nullptr, BUF_C, emb_w2, emb_b2, nullptr, BUF_B, NN, H512, H512, 1);

    // conv1: 512 -> 1024
    gemm(nullptr, BUF_B, c6_w, nullptr, nullptr, BUF_A, NN, H1024, H512, 0);
    k_gather<<<NN, 256>>>(BUF_A, BUF_C, c6_b);

    // conv2: 1024 -> 1024
    gemm(nullptr, BUF_C, c7_w, nullptr, nullptr, BUF_A, NN, H1024, H1024, 0);
    k_gather<<<NN, 256>>>(BUF_A, BUF_B, c7_b);

    // conv3: 1024 -> 1024
    gemm(nullptr, BUF_B, c8_w, nullptr, nullptr, BUF_A, NN, H1024, H1024, 0);
    k_gather<<<NN, 256>>>(BUF_A, BUF_C, c8_b);

    // mean pool (batch is sorted)
    dim3 pgrid(GG, H1024 / 256);
    k_pool2<<<pgrid, 256>>>(BUF_C, batch);

    // head
    gemm(nullptr, BUF_POOLED, fc1_w, fc1_b, nullptr, BUF_Z, GG, FC, H1024, 1);
    gemm(nullptr, BUF_Z, head_w, head_b, out, -1, GG, NCLS, FC, 0);
}

// round 7
// speedup vs baseline: 3.8393x; 1.6631x over previous
#include <cuda_runtime.h>
#include <cstdint>

#define NN    50000
#define EE    200000
#define GG    128
#define FIN   40
#define H512  512
#define H1024 1024
#define FC    2048
#define NCLS  345
#define NB_SCAN ((NN + 255) / 256)

// pre-rounded weight scratch offsets (floats)
#define W2R_OFF  0
#define C6_OFF   262144
#define C7_OFF   786432
#define C8_OFF   1835008
#define FC1_OFF  2883584
#define WR_TOTAL 4980736

// ---------------- scratch (static device globals; no allocations) ----------
__device__ float g_bufA[(size_t)NN * H1024];
__device__ float g_bufB[(size_t)NN * H1024];
__device__ float g_bufC[(size_t)NN * H1024];
__device__ float g_wr[WR_TOTAL];
__device__ float g_ew[EE];
__device__ float g_deg[NN];
__device__ float g_dis[NN];
__device__ float g_pooled[GG * H1024];
__device__ float g_z[GG * FC];
__device__ int   g_is64;

// CSR (by destination)
__device__ int   g_ecnt[NN];
__device__ int   g_rowstart[NN];
__device__ int   g_next[NN];
__device__ int   g_csr_src[EE];
__device__ float g_csr_w[EE];
__device__ int   g_blksum[NB_SCAN];

#define BUF_A      0
#define BUF_B      1
#define BUF_C      2
#define BUF_POOLED 3
#define BUF_Z      4
__device__ __forceinline__ float* sel(int id) {
    switch (id) {
        case BUF_A:      return g_bufA;
        case BUF_B:      return g_bufB;
        case BUF_C:      return g_bufC;
        case BUF_POOLED: return g_pooled;
        case BUF_Z:      return g_z;
    }
    return nullptr;
}

__device__ __forceinline__ int ld_idx(const void* p, long long i) {
    return g_is64 ? (int)((const long long*)p)[i] : ((const int*)p)[i];
}

__device__ __forceinline__ uint32_t f2tf(float x) {
    uint32_t u;
    asm("cvt.rna.tf32.f32 %0, %1;" : "=r"(u) : "f"(x));
    return u;
}
__device__ __forceinline__ float tf32r(float x) {
    uint32_t u;
    asm("cvt.rna.tf32.f32 %0, %1;" : "=r"(u) : "f"(x));
    return __uint_as_float(u);
}

#define CP_ASYNC16(dst_u32, src_ptr) \
    asm volatile("cp.async.ca.shared.global [%0], [%1], 16;\n" :: "r"(dst_u32), "l"(src_ptr))
#define CP_COMMIT() asm volatile("cp.async.commit_group;\n" ::: "memory")
#define CP_WAIT0()  asm volatile("cp.async.wait_group 0;\n" ::: "memory")
#define CP_WAIT1()  asm volatile("cp.async.wait_group 1;\n" ::: "memory")

// ---------------- dtype detection ------------------------------------------
__global__ void k_detect(const unsigned int* __restrict__ ei_words) {
    __shared__ int found;
    if (threadIdx.x == 0) found = 0;
    __syncthreads();
    for (int i = 1 + 2 * threadIdx.x; i < 4096; i += 2 * blockDim.x)
        if (ei_words[i] != 0u) found = 1;
    __syncthreads();
    if (threadIdx.x == 0) g_is64 = (found ? 0 : 1);
}

// ---------------- init ------------------------------------------------------
__global__ void k_init() {
    int i = blockIdx.x * blockDim.x + threadIdx.x;
    if (i < NN) { g_deg[i] = 1.0f; g_ecnt[i] = 0; }
}

// ---------------- weight pre-rounding (tf32 rna, once per launch) ----------
__global__ void k_round5(const float* __restrict__ w2, const float* __restrict__ c6,
                         const float* __restrict__ c7, const float* __restrict__ c8,
                         const float* __restrict__ f1) {
    int i = blockIdx.x * 256 + threadIdx.x;
    if (i >= WR_TOTAL) return;
    float v;
    if      (i < C6_OFF)  v = w2[i - W2R_OFF];
    else if (i < C7_OFF)  v = c6[i - C6_OFF];
    else if (i < C8_OFF)  v = c7[i - C7_OFF];
    else if (i < FC1_OFF) v = c8[i - C8_OFF];
    else                  v = f1[i - FC1_OFF];
    g_wr[i] = tf32r(v);
}

// ---------------- edge MLP --------------------------------------------------
__global__ void k_edge_mlp(const float* __restrict__ ea,
                           const float* __restrict__ w1, const float* __restrict__ b1,
                           const float* __restrict__ w2, const float* __restrict__ b2) {
    int e = blockIdx.x * blockDim.x + threadIdx.x;
    if (e >= EE) return;
    float a0 = ea[e * 3 + 0], a1 = ea[e * 3 + 1], a2 = ea[e * 3 + 2];
    float acc = b2[0];
#pragma unroll 8
    for (int h = 0; h < 64; h++) {
        float v = b1[h] + a0 * w1[h] + a1 * w1[64 + h] + a2 * w1[128 + h];
        acc += fmaxf(v, 0.0f) * w2[h];
    }
    g_ew[e] = 1.0f / (1.0f + expf(-acc));
}

// ---------------- degree + in-edge count -------------------------------------
__global__ void k_degcnt(const void* __restrict__ ei) {
    int e = blockIdx.x * blockDim.x + threadIdx.x;
    if (e >= EE) return;
    int d = ld_idx(ei, (long long)EE + e);
    if (d >= 0 && d < NN) {
        atomicAdd(&g_deg[d], g_ew[e]);
        atomicAdd(&g_ecnt[d], 1);
    }
}

__global__ void k_dis() {
    int i = blockIdx.x * blockDim.x + threadIdx.x;
    if (i >= NN) return;
    g_dis[i] = rsqrtf(g_deg[i]);
}

// ---------------- CSR build --------------------------------------------------
__global__ void k_scan_block() {
    __shared__ int s[256];
    int tid = threadIdx.x;
    int i = blockIdx.x * 256 + tid;
    int v = (i < NN) ? g_ecnt[i] : 0;
    s[tid] = v;
    __syncthreads();
#pragma unroll
    for (int off = 1; off < 256; off <<= 1) {
        int t = (tid >= off) ? s[tid - off] : 0;
        __syncthreads();
        s[tid] += t;
        __syncthreads();
    }
    if (i < NN) g_rowstart[i] = s[tid] - v;
    if (tid == 255) g_blksum[blockIdx.x] = s[tid];
}

__global__ void k_scan_tops() {
    if (threadIdx.x == 0 && blockIdx.x == 0) {
        int run = 0;
        for (int b = 0; b < NB_SCAN; b++) {
            int t = g_blksum[b];
            g_blksum[b] = run;
            run += t;
        }
    }
}

__global__ void k_scan_add() {
    int i = blockIdx.x * 256 + threadIdx.x;
    if (i >= NN) return;
    int r = g_rowstart[i] + g_blksum[blockIdx.x];
    g_rowstart[i] = r;
    g_next[i] = r;
}

__global__ void k_fill(const void* __restrict__ ei) {
    int e = blockIdx.x * blockDim.x + threadIdx.x;
    if (e >= EE) return;
    int s = ld_idx(ei, e);
    int d = ld_idx(ei, (long long)EE + e);
    if (s < 0 || s >= NN || d < 0 || d >= NN) return;
    int pos = atomicAdd(&g_next[d], 1);
    g_csr_src[pos] = s;
    g_csr_w[pos]   = g_dis[s] * g_ew[e] * g_dis[d];
}

// ---------------- FAST tf32 GEMM: cp.async double-buffered -------------------
// Requirements: K%16==0, N%128... (N%4==0 and full B tiles: N%128==0 in usage),
// inputs already tf32-rounded. A,C are scratch buffers; B = g_wr + bOff.
__global__ __launch_bounds__(256) void k_fastgemm(
    int aId, int bOff, const float* __restrict__ bias, int cId,
    int M, int N, int K, int doRelu, int doRound)
{
    const float* __restrict__ A = sel(aId);
    const float* __restrict__ B = g_wr + bOff;
    float* __restrict__ C       = sel(cId);

    __shared__ float As[2][128][20];
    __shared__ float Bs[2][16][132];

    const int tid  = threadIdx.x;
    const int wid  = tid >> 5;
    const int lane = tid & 31;
    const int grp  = lane >> 2;
    const int tg   = lane & 3;
    const int warp_m = wid & 1;
    const int warp_n = wid >> 1;

    const int blockRow = blockIdx.y * 128;
    const int blockCol = blockIdx.x * 128;

    float acc[4][4][4];
#pragma unroll
    for (int mi = 0; mi < 4; mi++)
#pragma unroll
        for (int ni = 0; ni < 4; ni++)
#pragma unroll
            for (int r = 0; r < 4; r++) acc[mi][ni][r] = 0.0f;

    const int kIters = K >> 4;

    // per-thread chunk coordinates (2 chunks A, 2 chunks B)
    int ar0 = tid >> 2,               ak0 = (tid & 3) << 2;         // chunk tid
    int ar1 = (tid + 256) >> 2,       ak1 = ((tid + 256) & 3) << 2; // chunk tid+256
    int br0 = tid >> 5,               bn0 = (tid & 31) << 2;
    int br1 = (tid + 256) >> 5,       bn1 = ((tid + 256) & 31) << 2;
    int agr0 = min(blockRow + ar0, M - 1);
    int agr1 = min(blockRow + ar1, M - 1);

    uint32_t asBase0 = (uint32_t)__cvta_generic_to_shared(&As[0][0][0]);
    uint32_t asBase1 = (uint32_t)__cvta_generic_to_shared(&As[1][0][0]);
    uint32_t bsBase0 = (uint32_t)__cvta_generic_to_shared(&Bs[0][0][0]);
    uint32_t bsBase1 = (uint32_t)__cvta_generic_to_shared(&Bs[1][0][0]);

    // issue tile 0
    {
        const int k0 = 0;
        CP_ASYNC16(asBase0 + (ar0 * 20 + ak0) * 4, A + (long long)agr0 * K + k0 + ak0);
        CP_ASYNC16(asBase0 + (ar1 * 20 + ak1) * 4, A + (long long)agr1 * K + k0 + ak1);
        CP_ASYNC16(bsBase0 + (br0 * 132 + bn0) * 4, B + (long long)(k0 + br0) * N + blockCol + bn0);
        CP_ASYNC16(bsBase0 + (br1 * 132 + bn1) * 4, B + (long long)(k0 + br1) * N + blockCol + bn1);
        CP_COMMIT();
    }

    for (int it = 0; it < kIters; it++) {
        const int buf = it & 1;
        if (it + 1 < kIters) {
            const int k0 = (it + 1) << 4;
            uint32_t aB = (buf ? asBase0 : asBase1);
            uint32_t bB = (buf ? bsBase0 : bsBase1);
            CP_ASYNC16(aB + (ar0 * 20 + ak0) * 4, A + (long long)agr0 * K + k0 + ak0);
            CP_ASYNC16(aB + (ar1 * 20 + ak1) * 4, A + (long long)agr1 * K + k0 + ak1);
            CP_ASYNC16(bB + (br0 * 132 + bn0) * 4, B + (long long)(k0 + br0) * N + blockCol + bn0);
            CP_ASYNC16(bB + (br1 * 132 + bn1) * 4, B + (long long)(k0 + br1) * N + blockCol + bn1);
            CP_COMMIT();
            CP_WAIT1();
        } else {
            CP_WAIT0();
        }
        __syncthreads();

#pragma unroll
        for (int ks = 0; ks < 2; ks++) {
            const int kb = ks * 8;
            uint32_t af[4][4], bf[4][2];
#pragma unroll
            for (int mi = 0; mi < 4; mi++) {
                int rb = warp_m * 64 + mi * 16;
                af[mi][0] = __float_as_uint(As[buf][rb + grp][kb + tg]);
                af[mi][1] = __float_as_uint(As[buf][rb + grp + 8][kb + tg]);
                af[mi][2] = __float_as_uint(As[buf][rb + grp][kb + tg + 4]);
                af[mi][3] = __float_as_uint(As[buf][rb + grp + 8][kb + tg + 4]);
            }
#pragma unroll
            for (int ni = 0; ni < 4; ni++) {
                int nb = warp_n * 32 + ni * 8;
                bf[ni][0] = __float_as_uint(Bs[buf][kb + tg][nb + grp]);
                bf[ni][1] = __float_as_uint(Bs[buf][kb + tg + 4][nb + grp]);
            }
#pragma unroll
            for (int mi = 0; mi < 4; mi++)
#pragma unroll
                for (int ni = 0; ni < 4; ni++) {
                    asm volatile(
                        "mma.sync.aligned.m16n8k8.row.col.f32.tf32.tf32.f32 "
                        "{%0,%1,%2,%3}, {%4,%5,%6,%7}, {%8,%9}, {%0,%1,%2,%3};\n"
                        : "+f"(acc[mi][ni][0]), "+f"(acc[mi][ni][1]),
                          "+f"(acc[mi][ni][2]), "+f"(acc[mi][ni][3])
                        : "r"(af[mi][0]), "r"(af[mi][1]), "r"(af[mi][2]), "r"(af[mi][3]),
                          "r"(bf[ni][0]), "r"(bf[ni][1]));
                }
        }
        __syncthreads();
    }

#pragma unroll
    for (int mi = 0; mi < 4; mi++) {
        int r0 = blockRow + warp_m * 64 + mi * 16 + grp;
        int r1 = r0 + 8;
#pragma unroll
        for (int ni = 0; ni < 4; ni++) {
            int c0 = blockCol + warp_n * 32 + ni * 8 + 2 * tg;
#pragma unroll
            for (int h = 0; h < 2; h++) {
                int c = c0 + h;
                float b = bias ? bias[c] : 0.0f;
                if (r0 < M) {
                    float v = acc[mi][ni][h] + b;
                    if (doRelu) v = fmaxf(v, 0.0f);
                    if (doRound) v = tf32r(v);
                    C[(long long)r0 * N + c] = v;
                }
                if (r1 < M) {
                    float v = acc[mi][ni][2 + h] + b;
                    if (doRelu) v = fmaxf(v, 0.0f);
                    if (doRound) v = tf32r(v);
                    C[(long long)r1 * N + c] = v;
                }
            }
        }
    }
}

// ---------------- SLOW tf32 GEMM (edge cases: emb1, head) -------------------
__global__ __launch_bounds__(256) void k_tf32gemm(
    const float* Aext, int aId,
    const float* __restrict__ B,
    const float* __restrict__ bias,
    float* Cext, int cId,
    int M, int N, int K, int doRelu, int doRound)
{
    const float* __restrict__ A = (aId >= 0) ? sel(aId) : Aext;
    float* __restrict__ C       = (cId >= 0) ? sel(cId) : Cext;

    __shared__ uint32_t As[16][132];
    __shared__ uint32_t Bs[16][132];

    const int tid  = threadIdx.x;
    const int wid  = tid >> 5;
    const int lane = tid & 31;
    const int grp  = lane >> 2;
    const int tg   = lane & 3;
    const int warp_m = wid & 1;
    const int warp_n = wid >> 1;

    const int blockRow = blockIdx.y * 128;
    const int blockCol = blockIdx.x * 128;
    const bool nAligned = ((N & 3) == 0);

    float acc[4][4][4];
#pragma unroll
    for (int mi = 0; mi < 4; mi++)
#pragma unroll
        for (int ni = 0; ni < 4; ni++)
#pragma unroll
            for (int r = 0; r < 4; r++) acc[mi][ni][r] = 0.0f;

    const int kIters = (K + 15) / 16;
    for (int it = 0; it < kIters; it++) {
        const int k0 = it * 16;
#pragma unroll
        for (int i = 0; i < 2; i++) {
            int idx = tid + i * 256;
            int row = idx >> 2;
            int c4  = (idx & 3) << 2;
            int gr = blockRow + row;
            int gk = k0 + c4;
            float v0 = 0, v1 = 0, v2 = 0, v3 = 0;
            if (gr < M) {
                const float* ap = A + (long long)gr * K + gk;
                if (gk + 3 < K) {
                    float4 v = *(const float4*)ap;
                    v0 = v.x; v1 = v.y; v2 = v.z; v3 = v.w;
                } else {
                    if (gk + 0 < K) v0 = ap[0];
                    if (gk + 1 < K) v1 = ap[1];
                    if (gk + 2 < K) v2 = ap[2];
                    if (gk + 3 < K) v3 = ap[3];
                }
            }
            As[c4 + 0][row] = f2tf(v0);
            As[c4 + 1][row] = f2tf(v1);
            As[c4 + 2][row] = f2tf(v2);
            As[c4 + 3][row] = f2tf(v3);
        }
#pragma unroll
        for (int i = 0; i < 2; i++) {
            int idx = tid + i * 256;
            int row = idx >> 5;
            int c4  = (idx & 31) << 2;
            int gk = k0 + row;
            int gc = blockCol + c4;
            float v0 = 0, v1 = 0, v2 = 0, v3 = 0;
            if (gk < K) {
                const float* bp = B + (long long)gk * N + gc;
                if (nAligned && gc + 3 < N) {
                    float4 v = *(const float4*)bp;
                    v0 = v.x; v1 = v.y; v2 = v.z; v3 = v.w;
                } else {
                    if (gc + 0 < N) v0 = bp[0];
                    if (gc + 1 < N) v1 = bp[1];
                    if (gc + 2 < N) v2 = bp[2];
                    if (gc + 3 < N) v3 = bp[3];
                }
            }
            Bs[row][c4 + 0] = f2tf(v0);
            Bs[row][c4 + 1] = f2tf(v1);
            Bs[row][c4 + 2] = f2tf(v2);
            Bs[row][c4 + 3] = f2tf(v3);
        }
        __syncthreads();

#pragma unroll
        for (int ks = 0; ks < 2; ks++) {
            const int kb = ks * 8;
            uint32_t af[4][4], bf[4][2];
#pragma unroll
            for (int mi = 0; mi < 4; mi++) {
                int rb = warp_m * 64 + mi * 16;
                af[mi][0] = As[kb + tg][rb + grp];
                af[mi][1] = As[kb + tg][rb + grp + 8];
                af[mi][2] = As[kb + tg + 4][rb + grp];
                af[mi][3] = As[kb + tg + 4][rb + grp + 8];
            }
#pragma unroll
            for (int ni = 0; ni < 4; ni++) {
                int nb = warp_n * 32 + ni * 8;
                bf[ni][0] = Bs[kb + tg][nb + grp];
                bf[ni][1] = Bs[kb + tg + 4][nb + grp];
            }
#pragma unroll
            for (int mi = 0; mi < 4; mi++)
#pragma unroll
                for (int ni = 0; ni < 4; ni++) {
                    asm volatile(
                        "mma.sync.aligned.m16n8k8.row.col.f32.tf32.tf32.f32 "
                        "{%0,%1,%2,%3}, {%4,%5,%6,%7}, {%8,%9}, {%0,%1,%2,%3};\n"
                        : "+f"(acc[mi][ni][0]), "+f"(acc[mi][ni][1]),
                          "+f"(acc[mi][ni][2]), "+f"(acc[mi][ni][3])
                        : "r"(af[mi][0]), "r"(af[mi][1]), "r"(af[mi][2]), "r"(af[mi][3]),
                          "r"(bf[ni][0]), "r"(bf[ni][1]));
                }
        }
        __syncthreads();
    }

#pragma unroll
    for (int mi = 0; mi < 4; mi++) {
        int r0 = blockRow + warp_m * 64 + mi * 16 + grp;
        int r1 = r0 + 8;
#pragma unroll
        for (int ni = 0; ni < 4; ni++) {
            int c0 = blockCol + warp_n * 32 + ni * 8 + 2 * tg;
#pragma unroll
            for (int h = 0; h < 2; h++) {
                int c = c0 + h;
                if (c >= N) continue;
                float b = bias ? bias[c] : 0.0f;
                if (r0 < M) {
                    float v = acc[mi][ni][h] + b;
                    if (doRelu) v = fmaxf(v, 0.0f);
                    if (doRound) v = tf32r(v);
                    C[(long long)r0 * N + c] = v;
                }
                if (r1 < M) {
                    float v = acc[mi][ni][2 + h] + b;
                    if (doRelu) v = fmaxf(v, 0.0f);
                    if (doRound) v = tf32r(v);
                    C[(long long)r1 * N + c] = v;
                }
            }
        }
    }
}

// ---------------- gather: out[n,:] = round(dis[n]^2 t[n,:] + sum w t[src,:]) -
// blockDim.x = F/4
__global__ void k_gather(int tId, int outId, int F4) {
    const float4* __restrict__ t4 = (const float4*)sel(tId);
    float4* __restrict__ o4       = (float4*)sel(outId);

    int node = blockIdx.x;
    int tid  = threadIdx.x;

    float d = g_dis[node];
    float sw = d * d;
    float4 v = t4[(long long)node * F4 + tid];
    float4 acc;
    acc.x = sw * v.x; acc.y = sw * v.y; acc.z = sw * v.z; acc.w = sw * v.w;

    int s = g_rowstart[node];
    int e = s + g_ecnt[node];
    for (int i = s; i < e; i++) {
        int src = g_csr_src[i];
        float w = g_csr_w[i];
        float4 u = t4[(long long)src * F4 + tid];
        acc.x += w * u.x; acc.y += w * u.y; acc.z += w * u.z; acc.w += w * u.w;
    }
    acc.x = tf32r(acc.x); acc.y = tf32r(acc.y);
    acc.z = tf32r(acc.z); acc.w = tf32r(acc.w);
    o4[(long long)node * F4 + tid] = acc;
}

// ---------------- segmented mean pooling (batch sorted), rounded ------------
__global__ void k_pool2(int hId, const void* __restrict__ batch) {
    const float* __restrict__ h = sel(hId);
    int g = blockIdx.x;
    int f = blockIdx.y * 256 + threadIdx.x;

    int lo = 0, hi = NN;
    while (lo < hi) { int mid = (lo + hi) >> 1; if (ld_idx(batch, mid) < g) lo = mid + 1; else hi = mid; }
    int start = lo;
    lo = start; hi = NN;
    while (lo < hi) { int mid = (lo + hi) >> 1; if (ld_idx(batch, mid) < g + 1) lo = mid + 1; else hi = mid; }
    int end = lo;

    float acc = 0.0f;
    for (int n = start; n < end; n++)
        acc += h[(long long)n * H1024 + f];
    float cnt = (float)(end - start);
    g_pooled[g * H1024 + f] = tf32r(acc / fmaxf(cnt, 1.0f));
}

// ---------------- host orchestration ---------------------------------------
static void fastgemm(int aId, int bOff, const float* bias, int cId,
                     int M, int N, int K, int relu, int rnd) {
    dim3 grid(N / 128, (M + 127) / 128);
    k_fastgemm<<<grid, 256>>>(aId, bOff, bias, cId, M, N, K, relu, rnd);
}
static void slowgemm(const float* Aext, int aId, const float* B, const float* bias,
                     float* Cext, int cId, int M, int N, int K, int relu, int rnd) {
    dim3 grid((N + 127) / 128, (M + 127) / 128);
    k_tf32gemm<<<grid, 256>>>(Aext, aId, B, bias, Cext, cId, M, N, K, relu, rnd);
}

extern "C" void kernel_launch(void* const* d_in, const int* in_sizes, int n_in,
                              void* d_out, int out_size) {
    const float* x         = (const float*)d_in[0];
    const float* edge_attr = (const float*)d_in[1];
    const void*  ei        = d_in[2];
    const void*  batch     = d_in[3];
    const float *emb_w1 = (const float*)d_in[4],  *emb_b1 = (const float*)d_in[5];
    const float *emb_w2 = (const float*)d_in[6],  *emb_b2 = (const float*)d_in[7];
    const float *ep_w1  = (const float*)d_in[8],  *ep_b1  = (const float*)d_in[9];
    const float *ep_w2  = (const float*)d_in[10], *ep_b2  = (const float*)d_in[11];
    const float *c6_w   = (const float*)d_in[12], *c6_b   = (const float*)d_in[13];
    const float *c7_w   = (const float*)d_in[14], *c7_b   = (const float*)d_in[15];
    const float *c8_w   = (const float*)d_in[16], *c8_b   = (const float*)d_in[17];
    const float *fc1_w  = (const float*)d_in[18], *fc1_b  = (const float*)d_in[19];
    const float *head_w = (const float*)d_in[20], *head_b = (const float*)d_in[21];
    float* out = (float*)d_out;

    // preprocessing: dtype, weights, edge weights, CSR
    k_detect<<<1, 256>>>((const unsigned int*)ei);
    k_init<<<NB_SCAN, 256>>>();
    k_round5<<<(WR_TOTAL + 255) / 256, 256>>>(emb_w2, c6_w, c7_w, c8_w, fc1_w);
    k_edge_mlp<<<(EE + 255) / 256, 256>>>(edge_attr, ep_w1, ep_b1, ep_w2, ep_b2);
    k_degcnt<<<(EE + 255) / 256, 256>>>(ei);
    k_dis<<<NB_SCAN, 256>>>();
    k_scan_block<<<NB_SCAN, 256>>>();
    k_scan_tops<<<1, 32>>>();
    k_scan_add<<<NB_SCAN, 256>>>();
    k_fill<<<(EE + 255) / 256, 256>>>(ei);

    // embedding MLP
    slowgemm(x, -1, emb_w1, emb_b1, nullptr, BUF_C, NN, H512, FIN, 1, 1);   // -> bufC (rounded)
    fastgemm(BUF_C, W2R_OFF, emb_b2, BUF_B, NN, H512, H512, 1, 0);          // h -> bufB

    // conv1: aggregate (512) then transform
    k_gather<<<NN, H512 / 4>>>(BUF_B, BUF_C, H512 / 4);                     // agg(h) -> bufC
    fastgemm(BUF_C, C6_OFF, c6_b, BUF_A, NN, H1024, H512, 1, 0);            // h1 -> bufA

    // conv2
    k_gather<<<NN, H1024 / 4>>>(BUF_A, BUF_C, H1024 / 4);
    fastgemm(BUF_C, C7_OFF, c7_b, BUF_B, NN, H1024, H1024, 1, 0);           // h2 -> bufB

    // conv3
    k_gather<<<NN, H1024 / 4>>>(BUF_B, BUF_A, H1024 / 4);
    fastgemm(BUF_A, C8_OFF, c8_b, BUF_C, NN, H1024, H1024, 1, 0);           // h3 -> bufC

    // mean pool (rounded)
    dim3 pgrid(GG, H1024 / 256);
    k_pool2<<<pgrid, 256>>>(BUF_C, batch);

    // head
    fastgemm(BUF_POOLED, FC1_OFF, fc1_b, BUF_Z, GG, FC, H1024, 1, 0);       // z
    slowgemm(nullptr, BUF_Z, head_w, head_b, out, -1, GG, NCLS, FC, 0, 0);
}

// round 9
// speedup vs baseline: 4.0408x; 1.0525x over previous
#include <cuda_runtime.h>
#include <cstdint>

#define NN    50000
#define EE    200000
#define GG    128
#define FIN   40
#define H512  512
#define H1024 1024
#define FC    2048
#define NCLS  345
#define NB_SCAN ((NN + 255) / 256)

// pre-rounded weight scratch offsets (floats), layout [K][N] (original)
#define W2R_OFF  0
#define C6_OFF   262144
#define C7_OFF   786432
#define C8_OFF   1835008
#define FC1_OFF  2883584
#define WR_TOTAL 4980736

// dynamic smem for fastgemm: As[2][128][20] + Bs[2][16][264] floats
#define FG_AS_FLOATS (2 * 128 * 20)
#define FG_BS_FLOATS (2 * 16 * 264)
#define FG_SMEM ((FG_AS_FLOATS + FG_BS_FLOATS) * 4)

// ---------------- scratch (static device globals; no allocations) ----------
__device__ float g_bufA[(size_t)NN * H1024];
__device__ float g_bufB[(size_t)NN * H1024];
__device__ float g_bufC[(size_t)NN * H1024];
__device__ float g_wr[WR_TOTAL];
__device__ float g_ew[EE];
__device__ float g_deg[NN];
__device__ float g_dis[NN];
__device__ float g_pooled[GG * H1024];
__device__ float g_z[GG * FC];
__device__ int   g_is64;

// CSR (by destination)
__device__ int   g_ecnt[NN];
__device__ int   g_rowstart[NN];
__device__ int   g_next[NN];
__device__ int   g_csr_src[EE];
__device__ float g_csr_w[EE];
__device__ int   g_blksum[NB_SCAN];

#define BUF_A      0
#define BUF_B      1
#define BUF_C      2
#define BUF_POOLED 3
#define BUF_Z      4
__device__ __forceinline__ float* sel(int id) {
    switch (id) {
        case BUF_A:      return g_bufA;
        case BUF_B:      return g_bufB;
        case BUF_C:      return g_bufC;
        case BUF_POOLED: return g_pooled;
        case BUF_Z:      return g_z;
    }
    return nullptr;
}

__device__ __forceinline__ int ld_idx(const void* p, long long i) {
    return g_is64 ? (int)((const long long*)p)[i] : ((const int*)p)[i];
}

__device__ __forceinline__ uint32_t f2tf(float x) {
    uint32_t u;
    asm("cvt.rna.tf32.f32 %0, %1;" : "=r"(u) : "f"(x));
    return u;
}
__device__ __forceinline__ float tf32r(float x) {
    uint32_t u;
    asm("cvt.rna.tf32.f32 %0, %1;" : "=r"(u) : "f"(x));
    return __uint_as_float(u);
}

#define CP_ASYNC16(dst_u32, src_ptr) \
    asm volatile("cp.async.ca.shared.global [%0], [%1], 16;\n" :: "r"(dst_u32), "l"(src_ptr))
#define CP_COMMIT() asm volatile("cp.async.commit_group;\n" ::: "memory")
#define CP_WAIT0()  asm volatile("cp.async.wait_group 0;\n" ::: "memory")
#define CP_WAIT1()  asm volatile("cp.async.wait_group 1;\n" ::: "memory")

// ---------------- dtype detection ------------------------------------------
__global__ void k_detect(const unsigned int* __restrict__ ei_words) {
    __shared__ int found;
    if (threadIdx.x == 0) found = 0;
    __syncthreads();
    for (int i = 1 + 2 * threadIdx.x; i < 4096; i += 2 * blockDim.x)
        if (ei_words[i] != 0u) found = 1;
    __syncthreads();
    if (threadIdx.x == 0) g_is64 = (found ? 0 : 1);
}

__global__ void k_init() {
    int i = blockIdx.x * blockDim.x + threadIdx.x;
    if (i < NN) { g_deg[i] = 1.0f; g_ecnt[i] = 0; }
}

// ---------------- weight pre-rounding (tf32 rna, once per launch) ----------
__global__ void k_round5(const float* __restrict__ w2, const float* __restrict__ c6,
                         const float* __restrict__ c7, const float* __restrict__ c8,
                         const float* __restrict__ f1) {
    int i = blockIdx.x * 256 + threadIdx.x;
    if (i >= WR_TOTAL) return;
    float v;
    if      (i < C6_OFF)  v = w2[i - W2R_OFF];
    else if (i < C7_OFF)  v = c6[i - C6_OFF];
    else if (i < C8_OFF)  v = c7[i - C7_OFF];
    else if (i < FC1_OFF) v = c8[i - C8_OFF];
    else                  v = f1[i - FC1_OFF];
    g_wr[i] = tf32r(v);
}

// ---------------- edge MLP --------------------------------------------------
__global__ void k_edge_mlp(const float* __restrict__ ea,
                           const float* __restrict__ w1, const float* __restrict__ b1,
                           const float* __restrict__ w2, const float* __restrict__ b2) {
    int e = blockIdx.x * blockDim.x + threadIdx.x;
    if (e >= EE) return;
    float a0 = ea[e * 3 + 0], a1 = ea[e * 3 + 1], a2 = ea[e * 3 + 2];
    float acc = b2[0];
#pragma unroll 8
    for (int h = 0; h < 64; h++) {
        float v = b1[h] + a0 * w1[h] + a1 * w1[64 + h] + a2 * w1[128 + h];
        acc += fmaxf(v, 0.0f) * w2[h];
    }
    g_ew[e] = 1.0f / (1.0f + expf(-acc));
}

__global__ void k_degcnt(const void* __restrict__ ei) {
    int e = blockIdx.x * blockDim.x + threadIdx.x;
    if (e >= EE) return;
    int d = ld_idx(ei, (long long)EE + e);
    if (d >= 0 && d < NN) {
        atomicAdd(&g_deg[d], g_ew[e]);
        atomicAdd(&g_ecnt[d], 1);
    }
}

__global__ void k_dis() {
    int i = blockIdx.x * blockDim.x + threadIdx.x;
    if (i >= NN) return;
    g_dis[i] = rsqrtf(g_deg[i]);
}

// ---------------- CSR build --------------------------------------------------
__global__ void k_scan_block() {
    __shared__ int s[256];
    int tid = threadIdx.x;
    int i = blockIdx.x * 256 + tid;
    int v = (i < NN) ? g_ecnt[i] : 0;
    s[tid] = v;
    __syncthreads();
#pragma unroll
    for (int off = 1; off < 256; off <<= 1) {
        int t = (tid >= off) ? s[tid - off] : 0;
        __syncthreads();
        s[tid] += t;
        __syncthreads();
    }
    if (i < NN) g_rowstart[i] = s[tid] - v;
    if (tid == 255) g_blksum[blockIdx.x] = s[tid];
}

__global__ void k_scan_tops() {
    if (threadIdx.x == 0 && blockIdx.x == 0) {
        int run = 0;
        for (int b = 0; b < NB_SCAN; b++) {
            int t = g_blksum[b];
            g_blksum[b] = run;
            run += t;
        }
    }
}

__global__ void k_scan_add() {
    int i = blockIdx.x * 256 + threadIdx.x;
    if (i >= NN) return;
    int r = g_rowstart[i] + g_blksum[blockIdx.x];
    g_rowstart[i] = r;
    g_next[i] = r;
}

__global__ void k_fill(const void* __restrict__ ei) {
    int e = blockIdx.x * blockDim.x + threadIdx.x;
    if (e >= EE) return;
    int s = ld_idx(ei, e);
    int d = ld_idx(ei, (long long)EE + e);
    if (s < 0 || s >= NN || d < 0 || d >= NN) return;
    int pos = atomicAdd(&g_next[d], 1);
    g_csr_src[pos] = s;
    g_csr_w[pos]   = g_dis[s] * g_ew[e] * g_dis[d];
}

// ---------------- FAST tf32 GEMM: cp.async, CTA 128x256, warp 64x64 ---------
// Requirements: K%16==0, N%256==0, inputs pre-rounded. B = g_wr + bOff, [K][N].
__global__ __launch_bounds__(256) void k_fastgemm(
    int aId, int bOff, const float* __restrict__ bias, int cId,
    int M, int N, int K, int doRelu, int doRound)
{
    extern __shared__ float smemF[];
    float (*As)[128][20] = (float(*)[128][20])smemF;                    // [buf][m][k]
    float (*Bs)[16][264] = (float(*)[16][264])(smemF + FG_AS_FLOATS);   // [buf][k][n]

    const float* __restrict__ A = sel(aId);
    const float* __restrict__ B = g_wr + bOff;
    float* __restrict__ C       = sel(cId);

    const int tid  = threadIdx.x;
    const int wid  = tid >> 5;
    const int lane = tid & 31;
    const int grp  = lane >> 2;
    const int tg   = lane & 3;
    const int warp_m = wid & 1;    // 2 warps along M (64 rows)
    const int warp_n = wid >> 1;   // 4 warps along N (64 cols)

    const int blockRow = blockIdx.y * 128;
    const int blockCol = blockIdx.x * 256;

    float acc[4][8][4];
#pragma unroll
    for (int mi = 0; mi < 4; mi++)
#pragma unroll
        for (int ni = 0; ni < 8; ni++)
#pragma unroll
            for (int r = 0; r < 4; r++) acc[mi][ni][r] = 0.0f;

    const int kIters = K >> 4;

    // A: 128x16 = 512 float4 chunks (2/thread); B: 16x256 = 1024 chunks (4/thread)
    int ar0 = tid >> 2,         ak0 = (tid & 3) << 2;
    int ar1 = (tid + 256) >> 2, ak1 = ((tid + 256) & 3) << 2;
    int agr0 = min(blockRow + ar0, M - 1);
    int agr1 = min(blockRow + ar1, M - 1);

    uint32_t asB[2], bsB[2];
    asB[0] = (uint32_t)__cvta_generic_to_shared(&As[0][0][0]);
    asB[1] = (uint32_t)__cvta_generic_to_shared(&As[1][0][0]);
    bsB[0] = (uint32_t)__cvta_generic_to_shared(&Bs[0][0][0]);
    bsB[1] = (uint32_t)__cvta_generic_to_shared(&Bs[1][0][0]);

    auto load_tile = [&](int it, int buf) {
        const int k0 = it << 4;
        CP_ASYNC16(asB[buf] + (ar0 * 20 + ak0) * 4, A + (size_t)agr0 * K + k0 + ak0);
        CP_ASYNC16(asB[buf] + (ar1 * 20 + ak1) * 4, A + (size_t)agr1 * K + k0 + ak1);
#pragma unroll
        for (int i = 0; i < 4; i++) {
            int q = tid + i * 256;
            int br = q >> 6;               // 0..15
            int bn = (q & 63) << 2;        // 0..252
            CP_ASYNC16(bsB[buf] + (br * 264 + bn) * 4, B + (size_t)(k0 + br) * N + blockCol + bn);
        }
        CP_COMMIT();
    };

    load_tile(0, 0);

    for (int it = 0; it < kIters; it++) {
        const int buf = it & 1;
        if (it + 1 < kIters) {
            load_tile(it + 1, buf ^ 1);
            CP_WAIT1();
        } else {
            CP_WAIT0();
        }
        __syncthreads();

#pragma unroll
        for (int ks = 0; ks < 2; ks++) {
            const int kb = ks * 8;
            uint32_t af[4][4], bf[8][2];
#pragma unroll
            for (int mi = 0; mi < 4; mi++) {
                int rb = warp_m * 64 + mi * 16;
                af[mi][0] = __float_as_uint(As[buf][rb + grp][kb + tg]);
                af[mi][1] = __float_as_uint(As[buf][rb + grp + 8][kb + tg]);
                af[mi][2] = __float_as_uint(As[buf][rb + grp][kb + tg + 4]);
                af[mi][3] = __float_as_uint(As[buf][rb + grp + 8][kb + tg + 4]);
            }
#pragma unroll
            for (int ni = 0; ni < 8; ni++) {
                int nb = warp_n * 64 + ni * 8;
                bf[ni][0] = __float_as_uint(Bs[buf][kb + tg][nb + grp]);
                bf[ni][1] = __float_as_uint(Bs[buf][kb + tg + 4][nb + grp]);
            }
#pragma unroll
            for (int mi = 0; mi < 4; mi++)
#pragma unroll
                for (int ni = 0; ni < 8; ni++) {
                    asm volatile(
                        "mma.sync.aligned.m16n8k8.row.col.f32.tf32.tf32.f32 "
                        "{%0,%1,%2,%3}, {%4,%5,%6,%7}, {%8,%9}, {%0,%1,%2,%3};\n"
                        : "+f"(acc[mi][ni][0]), "+f"(acc[mi][ni][1]),
                          "+f"(acc[mi][ni][2]), "+f"(acc[mi][ni][3])
                        : "r"(af[mi][0]), "r"(af[mi][1]), "r"(af[mi][2]), "r"(af[mi][3]),
                          "r"(bf[ni][0]), "r"(bf[ni][1]));
                }
        }
        __syncthreads();
    }

#pragma unroll
    for (int mi = 0; mi < 4; mi++) {
        int r0 = blockRow + warp_m * 64 + mi * 16 + grp;
        int r1 = r0 + 8;
#pragma unroll
        for (int ni = 0; ni < 8; ni++) {
            int c0 = blockCol + warp_n * 64 + ni * 8 + 2 * tg;
#pragma unroll
            for (int h = 0; h < 2; h++) {
                int c = c0 + h;
                float b = bias ? bias[c] : 0.0f;
                if (r0 < M) {
                    float v = acc[mi][ni][h] + b;
                    if (doRelu) v = fmaxf(v, 0.0f);
                    if (doRound) v = tf32r(v);
                    C[(size_t)r0 * N + c] = v;
                }
                if (r1 < M) {
                    float v = acc[mi][ni][2 + h] + b;
                    if (doRelu) v = fmaxf(v, 0.0f);
                    if (doRound) v = tf32r(v);
                    C[(size_t)r1 * N + c] = v;
                }
            }
        }
    }
}

// ---------------- SLOW tf32 GEMM (edge cases: emb1, head) -------------------
__global__ __launch_bounds__(256) void k_tf32gemm(
    const float* Aext, int aId,
    const float* __restrict__ B,
    const float* __restrict__ bias,
    float* Cext, int cId,
    int M, int N, int K, int doRelu, int doRound)
{
    const float* __restrict__ A = (aId >= 0) ? sel(aId) : Aext;
    float* __restrict__ C       = (cId >= 0) ? sel(cId) : Cext;

    __shared__ uint32_t As[16][132];
    __shared__ uint32_t Bs[16][132];

    const int tid  = threadIdx.x;
    const int wid  = tid >> 5;
    const int lane = tid & 31;
    const int grp  = lane >> 2;
    const int tg   = lane & 3;
    const int warp_m = wid & 1;
    const int warp_n = wid >> 1;

    const int blockRow = blockIdx.y * 128;
    const int blockCol = blockIdx.x * 128;
    const bool nAligned = ((N & 3) == 0);

    float acc[4][4][4];
#pragma unroll
    for (int mi = 0; mi < 4; mi++)
#pragma unroll
        for (int ni = 0; ni < 4; ni++)
#pragma unroll
            for (int r = 0; r < 4; r++) acc[mi][ni][r] = 0.0f;

    const int kIters = (K + 15) / 16;
    for (int it = 0; it < kIters; it++) {
        const int k0 = it * 16;
#pragma unroll
        for (int i = 0; i < 2; i++) {
            int idx = tid + i * 256;
            int row = idx >> 2;
            int c4  = (idx & 3) << 2;
            int gr = blockRow + row;
            int gk = k0 + c4;
            float v0 = 0, v1 = 0, v2 = 0, v3 = 0;
            if (gr < M) {
                const float* ap = A + (long long)gr * K + gk;
                if (gk + 3 < K) {
                    float4 v = *(const float4*)ap;
                    v0 = v.x; v1 = v.y; v2 = v.z; v3 = v.w;
                } else {
                    if (gk + 0 < K) v0 = ap[0];
                    if (gk + 1 < K) v1 = ap[1];
                    if (gk + 2 < K) v2 = ap[2];
                    if (gk + 3 < K) v3 = ap[3];
                }
            }
            As[c4 + 0][row] = f2tf(v0);
            As[c4 + 1][row] = f2tf(v1);
            As[c4 + 2][row] = f2tf(v2);
            As[c4 + 3][row] = f2tf(v3);
        }
#pragma unroll
        for (int i = 0; i < 2; i++) {
            int idx = tid + i * 256;
            int row = idx >> 5;
            int c4  = (idx & 31) << 2;
            int gk = k0 + row;
            int gc = blockCol + c4;
            float v0 = 0, v1 = 0, v2 = 0, v3 = 0;
            if (gk < K) {
                const float* bp = B + (long long)gk * N + gc;
                if (nAligned && gc + 3 < N) {
                    float4 v = *(const float4*)bp;
                    v0 = v.x; v1 = v.y; v2 = v.z; v3 = v.w;
                } else {
                    if (gc + 0 < N) v0 = bp[0];
                    if (gc + 1 < N) v1 = bp[1];
                    if (gc + 2 < N) v2 = bp[2];
                    if (gc + 3 < N) v3 = bp[3];
                }
            }
            Bs[row][c4 + 0] = f2tf(v0);
            Bs[row][c4 + 1] = f2tf(v1);
            Bs[row][c4 + 2] = f2tf(v2);
            Bs[row][c4 + 3] = f2tf(v3);
        }
        __syncthreads();

#pragma unroll
        for (int ks = 0; ks < 2; ks++) {
            const int kb = ks * 8;
            uint32_t af[4][4], bf[4][2];
#pragma unroll
            for (int mi = 0; mi < 4; mi++) {
                int rb = warp_m * 64 + mi * 16;
                af[mi][0] = As[kb + tg][rb + grp];
                af[mi][1] = As[kb + tg][rb + grp + 8];
                af[mi][2] = As[kb + tg + 4][rb + grp];
                af[mi][3] = As[kb + tg + 4][rb + grp + 8];
            }
#pragma unroll
            for (int ni = 0; ni < 4; ni++) {
                int nb = warp_n * 32 + ni * 8;
                bf[ni][0] = Bs[kb + tg][nb + grp];
                bf[ni][1] = Bs[kb + tg + 4][nb + grp];
            }
#pragma unroll
            for (int mi = 0; mi < 4; mi++)
#pragma unroll
                for (int ni = 0; ni < 4; ni++) {
                    asm volatile(
                        "mma.sync.aligned.m16n8k8.row.col.f32.tf32.tf32.f32 "
                        "{%0,%1,%2,%3}, {%4,%5,%6,%7}, {%8,%9}, {%0,%1,%2,%3};\n"
                        : "+f"(acc[mi][ni][0]), "+f"(acc[mi][ni][1]),
                          "+f"(acc[mi][ni][2]), "+f"(acc[mi][ni][3])
                        : "r"(af[mi][0]), "r"(af[mi][1]), "r"(af[mi][2]), "r"(af[mi][3]),
                          "r"(bf[ni][0]), "r"(bf[ni][1]));
                }
        }
        __syncthreads();
    }

#pragma unroll
    for (int mi = 0; mi < 4; mi++) {
        int r0 = blockRow + warp_m * 64 + mi * 16 + grp;
        int r1 = r0 + 8;
#pragma unroll
        for (int ni = 0; ni < 4; ni++) {
            int c0 = blockCol + warp_n * 32 + ni * 8 + 2 * tg;
#pragma unroll
            for (int h = 0; h < 2; h++) {
                int c = c0 + h;
                if (c >= N) continue;
                float b = bias ? bias[c] : 0.0f;
                if (r0 < M) {
                    float v = acc[mi][ni][h] + b;
                    if (doRelu) v = fmaxf(v, 0.0f);
                    if (doRound) v = tf32r(v);
                    C[(long long)r0 * N + c] = v;
                }
                if (r1 < M) {
                    float v = acc[mi][ni][2 + h] + b;
                    if (doRelu) v = fmaxf(v, 0.0f);
                    if (doRound) v = tf32r(v);
                    C[(long long)r1 * N + c] = v;
                }
            }
        }
    }
}

// ---------------- gather: out[n,:] = round(dis[n]^2 t[n,:] + sum w t[src,:]) -
__global__ void k_gather(int tId, int outId, int F4) {
    const float4* __restrict__ t4 = (const float4*)sel(tId);
    float4* __restrict__ o4       = (float4*)sel(outId);

    int node = blockIdx.x;
    int tid  = threadIdx.x;

    float d = g_dis[node];
    float sw = d * d;
    float4 v = t4[(long long)node * F4 + tid];
    float4 acc;
    acc.x = sw * v.x; acc.y = sw * v.y; acc.z = sw * v.z; acc.w = sw * v.w;

    int s = g_rowstart[node];
    int e = s + g_ecnt[node];
    for (int i = s; i < e; i++) {
        int src = g_csr_src[i];
        float w = g_csr_w[i];
        float4 u = t4[(long long)src * F4 + tid];
        acc.x += w * u.x; acc.y += w * u.y; acc.z += w * u.z; acc.w += w * u.w;
    }
    acc.x = tf32r(acc.x); acc.y = tf32r(acc.y);
    acc.z = tf32r(acc.z); acc.w = tf32r(acc.w);
    o4[(long long)node * F4 + tid] = acc;
}

// ---------------- segmented mean pooling (batch sorted), rounded ------------
__global__ void k_pool2(int hId, const void* __restrict__ batch) {
    const float* __restrict__ h = sel(hId);
    int g = blockIdx.x;
    int f = blockIdx.y * 256 + threadIdx.x;

    int lo = 0, hi = NN;
    while (lo < hi) { int mid = (lo + hi) >> 1; if (ld_idx(batch, mid) < g) lo = mid + 1; else hi = mid; }
    int start = lo;
    lo = start; hi = NN;
    while (lo < hi) { int mid = (lo + hi) >> 1; if (ld_idx(batch, mid) < g + 1) lo = mid + 1; else hi = mid; }
    int end = lo;

    float acc = 0.0f;
    for (int n = start; n < end; n++)
        acc += h[(long long)n * H1024 + f];
    float cnt = (float)(end - start);
    g_pooled[g * H1024 + f] = tf32r(acc / fmaxf(cnt, 1.0f));
}

// ---------------- host orchestration ---------------------------------------
static void fastgemm(int aId, int bOff, const float* bias, int cId,
                     int M, int N, int K, int relu, int rnd) {
    dim3 grid(N / 256, (M + 127) / 128);
    k_fastgemm<<<grid, 256, FG_SMEM>>>(aId, bOff, bias, cId, M, N, K, relu, rnd);
}
static void slowgemm(const float* Aext, int aId, const float* B, const float* bias,
                     float* Cext, int cId, int M, int N, int K, int relu, int rnd) {
    dim3 grid((N + 127) / 128, (M + 127) / 128);
    k_tf32gemm<<<grid, 256>>>(Aext, aId, B, bias, Cext, cId, M, N, K, relu, rnd);
}

extern "C" void kernel_launch(void* const* d_in, const int* in_sizes, int n_in,
                              void* d_out, int out_size) {
    const float* x         = (const float*)d_in[0];
    const float* edge_attr = (const float*)d_in[1];
    const void*  ei        = d_in[2];
    const void*  batch     = d_in[3];
    const float *emb_w1 = (const float*)d_in[4],  *emb_b1 = (const float*)d_in[5];
    const float *emb_w2 = (const float*)d_in[6],  *emb_b2 = (const float*)d_in[7];
    const float *ep_w1  = (const float*)d_in[8],  *ep_b1  = (const float*)d_in[9];
    const float *ep_w2  = (const float*)d_in[10], *ep_b2  = (const float*)d_in[11];
    const float *c6_w   = (const float*)d_in[12], *c6_b   = (const float*)d_in[13];
    const float *c7_w   = (const float*)d_in[14], *c7_b   = (const float*)d_in[15];
    const float *c8_w   = (const float*)d_in[16], *c8_b   = (const float*)d_in[17];
    const float *fc1_w  = (const float*)d_in[18], *fc1_b  = (const float*)d_in[19];
    const float *head_w = (const float*)d_in[20], *head_b = (const float*)d_in[21];
    float* out = (float*)d_out;

    cudaFuncSetAttribute(k_fastgemm, cudaFuncAttributeMaxDynamicSharedMemorySize, FG_SMEM);

    // preprocessing: dtype, weights, edge weights, CSR
    k_detect<<<1, 256>>>((const unsigned int*)ei);
    k_init<<<NB_SCAN, 256>>>();
    k_round5<<<(WR_TOTAL + 255) / 256, 256>>>(emb_w2, c6_w, c7_w, c8_w, fc1_w);
    k_edge_mlp<<<(EE + 255) / 256, 256>>>(edge_attr, ep_w1, ep_b1, ep_w2, ep_b2);
    k_degcnt<<<(EE + 255) / 256, 256>>>(ei);
    k_dis<<<NB_SCAN, 256>>>();
    k_scan_block<<<NB_SCAN, 256>>>();
    k_scan_tops<<<1, 32>>>();
    k_scan_add<<<NB_SCAN, 256>>>();
    k_fill<<<(EE + 255) / 256, 256>>>(ei);

    // embedding MLP
    slowgemm(x, -1, emb_w1, emb_b1, nullptr, BUF_C, NN, H512, FIN, 1, 1);   // -> bufC (rounded)
    fastgemm(BUF_C, W2R_OFF, emb_b2, BUF_B, NN, H512, H512, 1, 0);          // h -> bufB

    // conv1: aggregate (512) then transform
    k_gather<<<NN, H512 / 4>>>(BUF_B, BUF_C, H512 / 4);                     // agg(h) -> bufC
    fastgemm(BUF_C, C6_OFF, c6_b, BUF_A, NN, H1024, H512, 1, 0);            // h1 -> bufA

    // conv2
    k_gather<<<NN, H1024 / 4>>>(BUF_A, BUF_C, H1024 / 4);
    fastgemm(BUF_C, C7_OFF, c7_b, BUF_B, NN, H1024, H1024, 1, 0);           // h2 -> bufB

    // conv3
    k_gather<<<NN, H1024 / 4>>>(BUF_B, BUF_A, H1024 / 4);
    fastgemm(BUF_A, C8_OFF, c8_b, BUF_C, NN, H1024, H1024, 1, 0);           // h3 -> bufC

    // mean pool (rounded)
    dim3 pgrid(GG, H1024 / 256);
    k_pool2<<<pgrid, 256>>>(BUF_C, batch);

    // head
    fastgemm(BUF_POOLED, FC1_OFF, fc1_b, BUF_Z, GG, FC, H1024, 1, 0);       // z
    slowgemm(nullptr, BUF_Z, head_w, head_b, out, -1, GG, NCLS, FC, 0, 0);
}